// round 1
// baseline (speedup 1.0000x reference)
#include <cuda_runtime.h>
#include <math.h>

// Problem dims
#define B_   2
#define S_   2048
#define H_   2048
#define NH_  32
#define NKV_ 8
#define HD_  64

// Scratch (device globals: no allocations allowed)
__device__ float g_q[(size_t)B_ * S_ * NH_ * HD_];
__device__ float g_k[(size_t)B_ * S_ * NKV_ * HD_];
__device__ float g_v[(size_t)B_ * S_ * NKV_ * HD_];
__device__ float g_o[(size_t)B_ * S_ * NH_ * HD_];

typedef unsigned long long u64;

// ---- packed f32x2 helpers (Blackwell FFMA2 path) ----
__device__ __forceinline__ u64 ffma2(u64 a, u64 b, u64 c) {
    u64 d;
    asm("fma.rn.f32x2 %0, %1, %2, %3;" : "=l"(d) : "l"(a), "l"(b), "l"(c));
    return d;
}
__device__ __forceinline__ u64 fmul2(u64 a, u64 b) {
    u64 d;
    asm("mul.rn.f32x2 %0, %1, %2;" : "=l"(d) : "l"(a), "l"(b));
    return d;
}
__device__ __forceinline__ u64 pk2(float x, float y) {
    u64 r;
    asm("mov.b64 %0, {%1, %2};" : "=l"(r) : "f"(x), "f"(y));
    return r;
}
__device__ __forceinline__ float2 up2(u64 v) {
    float2 f;
    asm("mov.b64 {%0, %1}, %2;" : "=f"(f.x), "=f"(f.y) : "l"(v));
    return f;
}

// ============================================================================
// GEMM: C[M,N] = A[M,K] * W[N,K]^T, all row-major fp32.
// 128x128 tile, BK=8, 256 threads, 8x8 per-thread block computed as FFMA2
// pairs over N. Thread's 8 N-cols are split (tx*4 .. +3) and (64+tx*4 .. +3)
// so smem B reads are contiguous across tx (conflict-free LDS.128).
// ============================================================================
__global__ __launch_bounds__(256, 2) void gemm_nt_kernel(
    const float* __restrict__ A, const float* __restrict__ W,
    float* __restrict__ C, int M, int N, int K)
{
    __shared__ float As[8][128];
    __shared__ float Bs[8][128];
    const int tid = threadIdx.x;
    const int bm = blockIdx.y * 128, bn = blockIdx.x * 128;
    const int ty = tid >> 4, tx = tid & 15;
    const int lrow = tid >> 1, lk = (tid & 1) << 2;

    const float* Ap = A + (size_t)(bm + lrow) * K + lk;
    const float* Wp = W + (size_t)(bn + lrow) * K + lk;

    u64 acc[8][4];
#pragma unroll
    for (int i = 0; i < 8; i++)
#pragma unroll
        for (int j = 0; j < 4; j++) acc[i][j] = 0ULL;

    float4 ra = *(const float4*)Ap;
    float4 rb = *(const float4*)Wp;
    const int nt = K >> 3;
    for (int t = 0; t < nt; t++) {
        As[lk + 0][lrow] = ra.x; As[lk + 1][lrow] = ra.y;
        As[lk + 2][lrow] = ra.z; As[lk + 3][lrow] = ra.w;
        Bs[lk + 0][lrow] = rb.x; Bs[lk + 1][lrow] = rb.y;
        Bs[lk + 2][lrow] = rb.z; Bs[lk + 3][lrow] = rb.w;
        __syncthreads();
        if (t + 1 < nt) {
            ra = *(const float4*)(Ap + (size_t)(t + 1) * 8);
            rb = *(const float4*)(Wp + (size_t)(t + 1) * 8);
        }
#pragma unroll
        for (int kk = 0; kk < 8; kk++) {
            float4 a0 = *(const float4*)&As[kk][ty * 8];
            float4 a1 = *(const float4*)&As[kk][ty * 8 + 4];
            ulonglong2 b0 = *(const ulonglong2*)&Bs[kk][tx * 4];
            ulonglong2 b1 = *(const ulonglong2*)&Bs[kk][64 + tx * 4];
            float av[8] = {a0.x, a0.y, a0.z, a0.w, a1.x, a1.y, a1.z, a1.w};
#pragma unroll
            for (int i = 0; i < 8; i++) {
                u64 ap = pk2(av[i], av[i]);
                acc[i][0] = ffma2(ap, b0.x, acc[i][0]);
                acc[i][1] = ffma2(ap, b0.y, acc[i][1]);
                acc[i][2] = ffma2(ap, b1.x, acc[i][2]);
                acc[i][3] = ffma2(ap, b1.y, acc[i][3]);
            }
        }
        __syncthreads();
    }
#pragma unroll
    for (int i = 0; i < 8; i++) {
        float2 c0 = up2(acc[i][0]), c1 = up2(acc[i][1]);
        float2 c2 = up2(acc[i][2]), c3 = up2(acc[i][3]);
        size_t row = (size_t)(bm + ty * 8 + i);
        *(float4*)&C[row * N + bn + tx * 4]      = make_float4(c0.x, c0.y, c1.x, c1.y);
        *(float4*)&C[row * N + bn + 64 + tx * 4] = make_float4(c2.x, c2.y, c3.x, c3.y);
    }
}

// ============================================================================
// RoPE (in place), matching reference rotate_half convention.
// Also folds attention scale (1/sqrt(HD)) into Q.
// x layout: [B, S, nheads, HD]; each thread handles one (d, d+32) pair.
// ============================================================================
__global__ void rope_kernel(float* __restrict__ x, int nheads, float scale)
{
    int idx = blockIdx.x * blockDim.x + threadIdx.x;
    int total = B_ * S_ * nheads * 32;
    if (idx >= total) return;
    int d = idx & 31;
    int r = idx >> 5;
    int h = r % nheads; r /= nheads;
    int s = r % S_;
    int b = r / S_;

    float inv = (float)pow(10000.0, -(double)d / 32.0);
    float fr = (float)s * inv;
    float c, sn;
    sincosf(fr, &sn, &c);

    size_t base = (((size_t)b * S_ + s) * nheads + h) * HD_;
    float x0 = x[base + d], x1 = x[base + d + 32];
    x[base + d]      = (x0 * c - x1 * sn) * scale;
    x[base + d + 32] = (x1 * c + x0 * sn) * scale;
}

// ============================================================================
// Flash attention (causal, GQA), fp32, FFMA2 inner loops.
// Block = one (b, head, 64-row q-tile); 256 threads as 16x16; each thread owns
// a 4x4 S-block and 4x4 O-block. K tile is XOR-swizzled in smem (16B chunks,
// chunk ^= row>>2) so QK^T reads are conflict-free across tx.
// Online softmax stats reduced via half-warp butterfly shuffles.
// ============================================================================
__global__ __launch_bounds__(256, 2) void attn_kernel()
{
    extern __shared__ float smf[];
    float* Qs = smf;                // [64][64]
    float* Ks = smf + 64 * 64;      // [64][64] swizzled
    float* Vs = smf + 2 * 64 * 64;  // [64][64]
    float* Ps = smf + 3 * 64 * 64;  // [64][64]

    const int qt = (S_ / 64 - 1) - blockIdx.x;   // long blocks scheduled first
    const int h = blockIdx.y, b = blockIdx.z;
    const int hkv = h >> 2;                      // NREP = 4
    const int tid = threadIdx.x;
    const int ty = tid >> 4, tx = tid & 15;
    const int q0 = qt * 64;

    const int lr = tid >> 2;     // loader row 0..63
    const int lf = tid & 3;      // loader float4 slot base
    const int ksw = (lr >> 2) & 15;

    // load Q tile (pre-scaled by rope_kernel)
    {
        const float* qp = g_q + (((size_t)b * S_ + q0 + lr) * NH_ + h) * HD_;
#pragma unroll
        for (int rep = 0; rep < 4; rep++) {
            int f = lf + rep * 4;
            *(float4*)&Qs[lr * 64 + f * 4] = *(const float4*)&qp[f * 4];
        }
    }

    float m_r[4], l_r[4];
    u64 o2[4][2];
#pragma unroll
    for (int r = 0; r < 4; r++) {
        m_r[r] = -1e30f; l_r[r] = 0.f;
        o2[r][0] = 0ULL; o2[r][1] = 0ULL;
    }

    for (int j = 0; j <= qt; j++) {
        __syncthreads();   // prior PV / S reads of Ks,Vs,Ps done
        {
            const float* kp = g_k + (((size_t)b * S_ + j * 64 + lr) * NKV_ + hkv) * HD_;
            const float* vp = g_v + (((size_t)b * S_ + j * 64 + lr) * NKV_ + hkv) * HD_;
#pragma unroll
            for (int rep = 0; rep < 4; rep++) {
                int f = lf + rep * 4;
                *(float4*)&Ks[lr * 64 + ((f ^ ksw) * 4)] = *(const float4*)&kp[f * 4];
                *(float4*)&Vs[lr * 64 + f * 4]           = *(const float4*)&vp[f * 4];
            }
        }
        __syncthreads();

        // ---- S = Q K^T (pack over d) ----
        u64 s2[4][4];
#pragma unroll
        for (int r = 0; r < 4; r++)
#pragma unroll
            for (int c = 0; c < 4; c++) s2[r][c] = 0ULL;

#pragma unroll
        for (int d4 = 0; d4 < 16; d4++) {
            ulonglong2 qv[4], kv[4];
#pragma unroll
            for (int r = 0; r < 4; r++)
                qv[r] = *(const ulonglong2*)&Qs[(ty * 4 + r) * 64 + d4 * 4];
#pragma unroll
            for (int c = 0; c < 4; c++)
                kv[c] = *(const ulonglong2*)&Ks[(tx * 4 + c) * 64 + ((d4 ^ tx) & 15) * 4];
#pragma unroll
            for (int r = 0; r < 4; r++)
#pragma unroll
                for (int c = 0; c < 4; c++) {
                    s2[r][c] = ffma2(qv[r].x, kv[c].x, s2[r][c]);
                    s2[r][c] = ffma2(qv[r].y, kv[c].y, s2[r][c]);
                }
        }
        float sv[4][4];
#pragma unroll
        for (int r = 0; r < 4; r++)
#pragma unroll
            for (int c = 0; c < 4; c++) {
                float2 t = up2(s2[r][c]);
                sv[r][c] = t.x + t.y;
            }

        if (j == qt) {   // diagonal tile: causal mask
#pragma unroll
            for (int r = 0; r < 4; r++)
#pragma unroll
                for (int c = 0; c < 4; c++)
                    if (tx * 4 + c > ty * 4 + r) sv[r][c] = -1e30f;
        }

        // ---- online softmax (row stats via 16-lane butterfly) ----
#pragma unroll
        for (int r = 0; r < 4; r++) {
            float mx = fmaxf(fmaxf(sv[r][0], sv[r][1]), fmaxf(sv[r][2], sv[r][3]));
#pragma unroll
            for (int off = 1; off < 16; off <<= 1)
                mx = fmaxf(mx, __shfl_xor_sync(0xffffffffu, mx, off));
            float nm = fmaxf(m_r[r], mx);
            float alpha = __expf(m_r[r] - nm);
            float p0 = __expf(sv[r][0] - nm), p1 = __expf(sv[r][1] - nm);
            float p2 = __expf(sv[r][2] - nm), p3 = __expf(sv[r][3] - nm);
            float rs = p0 + p1 + p2 + p3;
#pragma unroll
            for (int off = 1; off < 16; off <<= 1)
                rs += __shfl_xor_sync(0xffffffffu, rs, off);
            l_r[r] = l_r[r] * alpha + rs;
            m_r[r] = nm;
            u64 a2 = pk2(alpha, alpha);
            o2[r][0] = fmul2(o2[r][0], a2);
            o2[r][1] = fmul2(o2[r][1], a2);
            *(float4*)&Ps[(ty * 4 + r) * 64 + tx * 4] = make_float4(p0, p1, p2, p3);
        }
        __syncthreads();

        // ---- O += P V (pack over dv) ----
#pragma unroll 4
        for (int ki = 0; ki < 64; ki += 2) {
            ulonglong2 va = *(const ulonglong2*)&Vs[ki * 64 + tx * 4];
            ulonglong2 vb = *(const ulonglong2*)&Vs[(ki + 1) * 64 + tx * 4];
#pragma unroll
            for (int r = 0; r < 4; r++) {
                float2 pp = *(const float2*)&Ps[(ty * 4 + r) * 64 + ki];
                u64 pa = pk2(pp.x, pp.x), pb = pk2(pp.y, pp.y);
                o2[r][0] = ffma2(pa, va.x, o2[r][0]);
                o2[r][1] = ffma2(pa, va.y, o2[r][1]);
                o2[r][0] = ffma2(pb, vb.x, o2[r][0]);
                o2[r][1] = ffma2(pb, vb.y, o2[r][1]);
            }
        }
    }

    // epilogue: O / l, write [b, s, h, d]
#pragma unroll
    for (int r = 0; r < 4; r++) {
        float inv = 1.0f / l_r[r];
        float2 a = up2(o2[r][0]), bq = up2(o2[r][1]);
        size_t row = (size_t)b * S_ + (q0 + ty * 4 + r);
        *(float4*)&g_o[(row * NH_ + h) * HD_ + tx * 4] =
            make_float4(a.x * inv, a.y * inv, bq.x * inv, bq.y * inv);
    }
}

// ============================================================================
extern "C" void kernel_launch(void* const* d_in, const int* in_sizes, int n_in,
                              void* d_out, int out_size)
{
    const float* hs = (const float*)d_in[0];
    const float* Wq = (const float*)d_in[1];
    const float* Wk = (const float*)d_in[2];
    const float* Wv = (const float*)d_in[3];
    const float* Wo = (const float*)d_in[4];
    float* out = (float*)d_out;

    float *qp, *kp, *vp, *op;
    cudaGetSymbolAddress((void**)&qp, g_q);
    cudaGetSymbolAddress((void**)&kp, g_k);
    cudaGetSymbolAddress((void**)&vp, g_v);
    cudaGetSymbolAddress((void**)&op, g_o);

    const int M = B_ * S_;   // 4096

    // QKV projections
    gemm_nt_kernel<<<dim3((NH_ * HD_) / 128, M / 128), 256>>>(hs, Wq, qp, M, NH_ * HD_, H_);
    gemm_nt_kernel<<<dim3((NKV_ * HD_) / 128, M / 128), 256>>>(hs, Wk, kp, M, NKV_ * HD_, H_);
    gemm_nt_kernel<<<dim3((NKV_ * HD_) / 128, M / 128), 256>>>(hs, Wv, vp, M, NKV_ * HD_, H_);

    // RoPE (scale 1/sqrt(64) folded into Q)
    rope_kernel<<<(B_ * S_ * NH_ * 32 + 255) / 256, 256>>>(qp, NH_, 0.125f);
    rope_kernel<<<(B_ * S_ * NKV_ * 32 + 255) / 256, 256>>>(kp, NKV_, 1.0f);

    // attention
    cudaFuncSetAttribute(attn_kernel, cudaFuncAttributeMaxDynamicSharedMemorySize, 65536);
    attn_kernel<<<dim3(S_ / 64, NH_, B_), 256, 65536>>>();

    // output projection
    gemm_nt_kernel<<<dim3(H_ / 128, M / 128), 256>>>(op, Wo, out, M, H_, H_);
}

// round 2
// speedup vs baseline: 1.3244x; 1.3244x over previous
#include <cuda_runtime.h>
#include <math.h>

// Problem dims
#define B_   2
#define S_   2048
#define H_   2048
#define NH_  32
#define NKV_ 8
#define HD_  64

// Scratch (device globals: no allocations allowed)
__device__ float g_q[(size_t)B_ * S_ * NH_ * HD_];
__device__ float g_k[(size_t)B_ * S_ * NKV_ * HD_];
__device__ float g_v[(size_t)B_ * S_ * NKV_ * HD_];
__device__ float g_o[(size_t)B_ * S_ * NH_ * HD_];

typedef unsigned long long u64;

// ---- packed f32x2 helpers (Blackwell FFMA2 path) ----
__device__ __forceinline__ u64 ffma2(u64 a, u64 b, u64 c) {
    u64 d;
    asm("fma.rn.f32x2 %0, %1, %2, %3;" : "=l"(d) : "l"(a), "l"(b), "l"(c));
    return d;
}
__device__ __forceinline__ u64 fmul2(u64 a, u64 b) {
    u64 d;
    asm("mul.rn.f32x2 %0, %1, %2;" : "=l"(d) : "l"(a), "l"(b));
    return d;
}
__device__ __forceinline__ u64 pk2(float x, float y) {
    u64 r;
    asm("mov.b64 %0, {%1, %2};" : "=l"(r) : "f"(x), "f"(y));
    return r;
}
__device__ __forceinline__ float2 up2(u64 v) {
    float2 f;
    asm("mov.b64 {%0, %1}, %2;" : "=f"(f.x), "=f"(f.y) : "l"(v));
    return f;
}

// ============================================================================
// GEMM: C[M,N] = A[M,K] * W[N,K]^T, all row-major fp32.
// 128x128 tile, BK=16, 256 threads, 8x8 per-thread block computed as FFMA2
// pairs over N. Thread's 8 N-cols are split (tx*4 .. +3) and (64+tx*4 .. +3)
// so smem B reads are contiguous across tx (conflict-free LDS.128).
// ============================================================================
__global__ __launch_bounds__(256, 2) void gemm_nt_kernel(
    const float* __restrict__ A, const float* __restrict__ W,
    float* __restrict__ C, int M, int N, int K)
{
    __shared__ float As[16][128];
    __shared__ float Bs[16][128];
    const int tid = threadIdx.x;
    const int bm = blockIdx.y * 128, bn = blockIdx.x * 128;
    const int ty = tid >> 4, tx = tid & 15;
    const int lrow = tid >> 1, lk = (tid & 1) << 3;

    const float* Ap = A + (size_t)(bm + lrow) * K + lk;
    const float* Wp = W + (size_t)(bn + lrow) * K + lk;

    u64 acc[8][4];
#pragma unroll
    for (int i = 0; i < 8; i++)
#pragma unroll
        for (int j = 0; j < 4; j++) acc[i][j] = 0ULL;

    float4 ra0 = *(const float4*)Ap;
    float4 ra1 = *(const float4*)(Ap + 4);
    float4 rb0 = *(const float4*)Wp;
    float4 rb1 = *(const float4*)(Wp + 4);
    const int nt = K >> 4;
    for (int t = 0; t < nt; t++) {
        As[lk + 0][lrow] = ra0.x; As[lk + 1][lrow] = ra0.y;
        As[lk + 2][lrow] = ra0.z; As[lk + 3][lrow] = ra0.w;
        As[lk + 4][lrow] = ra1.x; As[lk + 5][lrow] = ra1.y;
        As[lk + 6][lrow] = ra1.z; As[lk + 7][lrow] = ra1.w;
        Bs[lk + 0][lrow] = rb0.x; Bs[lk + 1][lrow] = rb0.y;
        Bs[lk + 2][lrow] = rb0.z; Bs[lk + 3][lrow] = rb0.w;
        Bs[lk + 4][lrow] = rb1.x; Bs[lk + 5][lrow] = rb1.y;
        Bs[lk + 6][lrow] = rb1.z; Bs[lk + 7][lrow] = rb1.w;
        __syncthreads();
        if (t + 1 < nt) {
            const float* An = Ap + (size_t)(t + 1) * 16;
            const float* Wn = Wp + (size_t)(t + 1) * 16;
            ra0 = *(const float4*)An;  ra1 = *(const float4*)(An + 4);
            rb0 = *(const float4*)Wn;  rb1 = *(const float4*)(Wn + 4);
        }
#pragma unroll
        for (int kk = 0; kk < 16; kk++) {
            float4 a0 = *(const float4*)&As[kk][ty * 8];
            float4 a1 = *(const float4*)&As[kk][ty * 8 + 4];
            ulonglong2 b0 = *(const ulonglong2*)&Bs[kk][tx * 4];
            ulonglong2 b1 = *(const ulonglong2*)&Bs[kk][64 + tx * 4];
            float av[8] = {a0.x, a0.y, a0.z, a0.w, a1.x, a1.y, a1.z, a1.w};
#pragma unroll
            for (int i = 0; i < 8; i++) {
                u64 ap = pk2(av[i], av[i]);
                acc[i][0] = ffma2(ap, b0.x, acc[i][0]);
                acc[i][1] = ffma2(ap, b0.y, acc[i][1]);
                acc[i][2] = ffma2(ap, b1.x, acc[i][2]);
                acc[i][3] = ffma2(ap, b1.y, acc[i][3]);
            }
        }
        __syncthreads();
    }
#pragma unroll
    for (int i = 0; i < 8; i++) {
        float2 c0 = up2(acc[i][0]), c1 = up2(acc[i][1]);
        float2 c2 = up2(acc[i][2]), c3 = up2(acc[i][3]);
        size_t row = (size_t)(bm + ty * 8 + i);
        *(float4*)&C[row * N + bn + tx * 4]      = make_float4(c0.x, c0.y, c1.x, c1.y);
        *(float4*)&C[row * N + bn + 64 + tx * 4] = make_float4(c2.x, c2.y, c3.x, c3.y);
    }
}

// ============================================================================
// RoPE (in place), matching reference rotate_half convention.
// Pure fp32 (NO fp64 pow — that cost 639us last round).
// Also folds attention scale (1/sqrt(HD)) into Q.
// x layout: [B, S, nheads, HD]; each thread handles one (d, d+32) pair.
// ============================================================================
__global__ void rope_kernel(float* __restrict__ x, int nheads, float scale)
{
    int idx = blockIdx.x * blockDim.x + threadIdx.x;
    int total = B_ * S_ * nheads * 32;
    if (idx >= total) return;
    int d = idx & 31;
    int r = idx >> 5;
    int h = r % nheads; r /= nheads;
    int s = r % S_;
    int b = r / S_;

    // inv_freq = 10000^(-d/32) = exp2(-d * log2(10000)/32), fp32 only
    float inv = exp2f((float)d * -0.41524101186f);
    float fr = (float)s * inv;
    float c, sn;
    sincosf(fr, &sn, &c);

    size_t base = (((size_t)b * S_ + s) * nheads + h) * HD_;
    float x0 = x[base + d], x1 = x[base + d + 32];
    x[base + d]      = (x0 * c - x1 * sn) * scale;
    x[base + d + 32] = (x1 * c + x0 * sn) * scale;
}

// ============================================================================
// Flash attention (causal, GQA), fp32, FFMA2 inner loops.
// Block = one (b, head, 64-row q-tile); 256 threads as 16x16; each thread owns
// a 4x4 S-block and 4x4 O-block. K tile is XOR-swizzled in smem (16B chunks,
// chunk ^= row>>2) so QK^T reads are conflict-free across tx.
// Online softmax stats reduced via half-warp butterfly shuffles.
// ============================================================================
__global__ __launch_bounds__(256, 2) void attn_kernel()
{
    extern __shared__ float smf[];
    float* Qs = smf;                // [64][64]
    float* Ks = smf + 64 * 64;      // [64][64] swizzled
    float* Vs = smf + 2 * 64 * 64;  // [64][64]
    float* Ps = smf + 3 * 64 * 64;  // [64][64]

    const int qt = (S_ / 64 - 1) - blockIdx.x;   // long blocks scheduled first
    const int h = blockIdx.y, b = blockIdx.z;
    const int hkv = h >> 2;                      // NREP = 4
    const int tid = threadIdx.x;
    const int ty = tid >> 4, tx = tid & 15;
    const int q0 = qt * 64;

    const int lr = tid >> 2;     // loader row 0..63
    const int lf = tid & 3;      // loader float4 slot base
    const int ksw = (lr >> 2) & 15;

    // load Q tile (pre-scaled by rope_kernel)
    {
        const float* qp = g_q + (((size_t)b * S_ + q0 + lr) * NH_ + h) * HD_;
#pragma unroll
        for (int rep = 0; rep < 4; rep++) {
            int f = lf + rep * 4;
            *(float4*)&Qs[lr * 64 + f * 4] = *(const float4*)&qp[f * 4];
        }
    }

    float m_r[4], l_r[4];
    u64 o2[4][2];
#pragma unroll
    for (int r = 0; r < 4; r++) {
        m_r[r] = -1e30f; l_r[r] = 0.f;
        o2[r][0] = 0ULL; o2[r][1] = 0ULL;
    }

    for (int j = 0; j <= qt; j++) {
        __syncthreads();   // prior PV / S reads of Ks,Vs,Ps done
        {
            const float* kp = g_k + (((size_t)b * S_ + j * 64 + lr) * NKV_ + hkv) * HD_;
            const float* vp = g_v + (((size_t)b * S_ + j * 64 + lr) * NKV_ + hkv) * HD_;
#pragma unroll
            for (int rep = 0; rep < 4; rep++) {
                int f = lf + rep * 4;
                *(float4*)&Ks[lr * 64 + ((f ^ ksw) * 4)] = *(const float4*)&kp[f * 4];
                *(float4*)&Vs[lr * 64 + f * 4]           = *(const float4*)&vp[f * 4];
            }
        }
        __syncthreads();

        // ---- S = Q K^T (pack over d) ----
        u64 s2[4][4];
#pragma unroll
        for (int r = 0; r < 4; r++)
#pragma unroll
            for (int c = 0; c < 4; c++) s2[r][c] = 0ULL;

#pragma unroll
        for (int d4 = 0; d4 < 16; d4++) {
            ulonglong2 qv[4], kv[4];
#pragma unroll
            for (int r = 0; r < 4; r++)
                qv[r] = *(const ulonglong2*)&Qs[(ty * 4 + r) * 64 + d4 * 4];
#pragma unroll
            for (int c = 0; c < 4; c++)
                kv[c] = *(const ulonglong2*)&Ks[(tx * 4 + c) * 64 + ((d4 ^ tx) & 15) * 4];
#pragma unroll
            for (int r = 0; r < 4; r++)
#pragma unroll
                for (int c = 0; c < 4; c++) {
                    s2[r][c] = ffma2(qv[r].x, kv[c].x, s2[r][c]);
                    s2[r][c] = ffma2(qv[r].y, kv[c].y, s2[r][c]);
                }
        }
        float sv[4][4];
#pragma unroll
        for (int r = 0; r < 4; r++)
#pragma unroll
            for (int c = 0; c < 4; c++) {
                float2 t = up2(s2[r][c]);
                sv[r][c] = t.x + t.y;
            }

        if (j == qt) {   // diagonal tile: causal mask
#pragma unroll
            for (int r = 0; r < 4; r++)
#pragma unroll
                for (int c = 0; c < 4; c++)
                    if (tx * 4 + c > ty * 4 + r) sv[r][c] = -1e30f;
        }

        // ---- online softmax (row stats via 16-lane butterfly) ----
#pragma unroll
        for (int r = 0; r < 4; r++) {
            float mx = fmaxf(fmaxf(sv[r][0], sv[r][1]), fmaxf(sv[r][2], sv[r][3]));
#pragma unroll
            for (int off = 1; off < 16; off <<= 1)
                mx = fmaxf(mx, __shfl_xor_sync(0xffffffffu, mx, off));
            float nm = fmaxf(m_r[r], mx);
            float alpha = __expf(m_r[r] - nm);
            float p0 = __expf(sv[r][0] - nm), p1 = __expf(sv[r][1] - nm);
            float p2 = __expf(sv[r][2] - nm), p3 = __expf(sv[r][3] - nm);
            float rs = p0 + p1 + p2 + p3;
#pragma unroll
            for (int off = 1; off < 16; off <<= 1)
                rs += __shfl_xor_sync(0xffffffffu, rs, off);
            l_r[r] = l_r[r] * alpha + rs;
            m_r[r] = nm;
            u64 a2 = pk2(alpha, alpha);
            o2[r][0] = fmul2(o2[r][0], a2);
            o2[r][1] = fmul2(o2[r][1], a2);
            *(float4*)&Ps[(ty * 4 + r) * 64 + tx * 4] = make_float4(p0, p1, p2, p3);
        }
        __syncthreads();

        // ---- O += P V (pack over dv) ----
#pragma unroll 4
        for (int ki = 0; ki < 64; ki += 2) {
            ulonglong2 va = *(const ulonglong2*)&Vs[ki * 64 + tx * 4];
            ulonglong2 vb = *(const ulonglong2*)&Vs[(ki + 1) * 64 + tx * 4];
#pragma unroll
            for (int r = 0; r < 4; r++) {
                float2 pp = *(const float2*)&Ps[(ty * 4 + r) * 64 + ki];
                u64 pa = pk2(pp.x, pp.x), pb = pk2(pp.y, pp.y);
                o2[r][0] = ffma2(pa, va.x, o2[r][0]);
                o2[r][1] = ffma2(pa, va.y, o2[r][1]);
                o2[r][0] = ffma2(pb, vb.x, o2[r][0]);
                o2[r][1] = ffma2(pb, vb.y, o2[r][1]);
            }
        }
    }

    // epilogue: O / l, write [b, s, h, d]
#pragma unroll
    for (int r = 0; r < 4; r++) {
        float inv = 1.0f / l_r[r];
        float2 a = up2(o2[r][0]), bq = up2(o2[r][1]);
        size_t row = (size_t)b * S_ + (q0 + ty * 4 + r);
        *(float4*)&g_o[(row * NH_ + h) * HD_ + tx * 4] =
            make_float4(a.x * inv, a.y * inv, bq.x * inv, bq.y * inv);
    }
}

// ============================================================================
extern "C" void kernel_launch(void* const* d_in, const int* in_sizes, int n_in,
                              void* d_out, int out_size)
{
    const float* hs = (const float*)d_in[0];
    const float* Wq = (const float*)d_in[1];
    const float* Wk = (const float*)d_in[2];
    const float* Wv = (const float*)d_in[3];
    const float* Wo = (const float*)d_in[4];
    float* out = (float*)d_out;

    float *qp, *kp, *vp, *op;
    cudaGetSymbolAddress((void**)&qp, g_q);
    cudaGetSymbolAddress((void**)&kp, g_k);
    cudaGetSymbolAddress((void**)&vp, g_v);
    cudaGetSymbolAddress((void**)&op, g_o);

    const int M = B_ * S_;   // 4096

    // QKV projections
    gemm_nt_kernel<<<dim3((NH_ * HD_) / 128, M / 128), 256>>>(hs, Wq, qp, M, NH_ * HD_, H_);
    gemm_nt_kernel<<<dim3((NKV_ * HD_) / 128, M / 128), 256>>>(hs, Wk, kp, M, NKV_ * HD_, H_);
    gemm_nt_kernel<<<dim3((NKV_ * HD_) / 128, M / 128), 256>>>(hs, Wv, vp, M, NKV_ * HD_, H_);

    // RoPE (scale 1/sqrt(64) folded into Q)
    rope_kernel<<<(B_ * S_ * NH_ * 32 + 255) / 256, 256>>>(qp, NH_, 0.125f);
    rope_kernel<<<(B_ * S_ * NKV_ * 32 + 255) / 256, 256>>>(kp, NKV_, 1.0f);

    // attention
    cudaFuncSetAttribute(attn_kernel, cudaFuncAttributeMaxDynamicSharedMemorySize, 65536);
    attn_kernel<<<dim3(S_ / 64, NH_, B_), 256, 65536>>>();

    // output projection
    gemm_nt_kernel<<<dim3(H_ / 128, M / 128), 256>>>(op, Wo, out, M, H_, H_);
}

// round 5
// speedup vs baseline: 1.8014x; 1.3602x over previous
#include <cuda_runtime.h>
#include <cuda_bf16.h>
#include <math.h>
#include <cstdint>

// Problem dims
#define B_   2
#define S_   2048
#define H_   2048
#define NH_  32
#define NKV_ 8
#define HD_  64

// fp32 scratch
__device__ float g_q[(size_t)B_ * S_ * NH_ * HD_];
__device__ float g_k[(size_t)B_ * S_ * NKV_ * HD_];
__device__ float g_v[(size_t)B_ * S_ * NKV_ * HD_];
__device__ float g_o[(size_t)B_ * S_ * NH_ * HD_];

// bf16 split scratch (hi/lo)
__device__ __nv_bfloat16 g_hs_hi[(size_t)B_ * S_ * H_];
__device__ __nv_bfloat16 g_hs_lo[(size_t)B_ * S_ * H_];
__device__ __nv_bfloat16 g_w_hi[(size_t)H_ * H_];
__device__ __nv_bfloat16 g_w_lo[(size_t)H_ * H_];
__device__ __nv_bfloat16 g_oh_hi[(size_t)B_ * S_ * NH_ * HD_];
__device__ __nv_bfloat16 g_oh_lo[(size_t)B_ * S_ * NH_ * HD_];

typedef unsigned long long u64;

// ---- packed f32x2 helpers (used by attention) ----
__device__ __forceinline__ u64 ffma2(u64 a, u64 b, u64 c) {
    u64 d;
    asm("fma.rn.f32x2 %0, %1, %2, %3;" : "=l"(d) : "l"(a), "l"(b), "l"(c));
    return d;
}
__device__ __forceinline__ u64 fmul2(u64 a, u64 b) {
    u64 d;
    asm("mul.rn.f32x2 %0, %1, %2;" : "=l"(d) : "l"(a), "l"(b));
    return d;
}
__device__ __forceinline__ u64 pk2(float x, float y) {
    u64 r;
    asm("mov.b64 %0, {%1, %2};" : "=l"(r) : "f"(x), "f"(y));
    return r;
}
__device__ __forceinline__ float2 up2(u64 v) {
    float2 f;
    asm("mov.b64 {%0, %1}, %2;" : "=f"(f.x), "=f"(f.y) : "l"(v));
    return f;
}

// ---- mma.sync / ldmatrix / cp.async helpers (non-"a" PTX, sm_80+) ----
__device__ __forceinline__ uint32_t smem_u32(const void* p) {
    uint32_t a;
    asm("{ .reg .u64 t; cvta.to.shared.u64 t, %1; cvt.u32.u64 %0, t; }" : "=r"(a) : "l"(p));
    return a;
}
__device__ __forceinline__ void ldmx4(uint32_t* r, uint32_t addr) {
    asm volatile("ldmatrix.sync.aligned.m8n8.x4.shared.b16 {%0,%1,%2,%3}, [%4];"
                 : "=r"(r[0]), "=r"(r[1]), "=r"(r[2]), "=r"(r[3]) : "r"(addr));
}
__device__ __forceinline__ void mma16816(float* c, const uint32_t* a, uint32_t b0, uint32_t b1) {
    asm volatile("mma.sync.aligned.m16n8k16.row.col.f32.bf16.bf16.f32 "
                 "{%0,%1,%2,%3}, {%4,%5,%6,%7}, {%8,%9}, {%0,%1,%2,%3};"
                 : "+f"(c[0]), "+f"(c[1]), "+f"(c[2]), "+f"(c[3])
                 : "r"(a[0]), "r"(a[1]), "r"(a[2]), "r"(a[3]), "r"(b0), "r"(b1));
}
__device__ __forceinline__ void cp16(uint32_t s, const void* g) {
    asm volatile("cp.async.ca.shared.global [%0], [%1], 16;" :: "r"(s), "l"(g));
}
#define CP_COMMIT() asm volatile("cp.async.commit_group;" ::: "memory")
#define CP_WAIT0()  asm volatile("cp.async.wait_group 0;" ::: "memory")

// ============================================================================
// split: fp32 -> bf16 hi + bf16 lo (x ~= hi + lo)
// ============================================================================
__global__ void split_kernel(const float* __restrict__ x,
                             __nv_bfloat16* __restrict__ hi,
                             __nv_bfloat16* __restrict__ lo, int n4)
{
    int i = blockIdx.x * blockDim.x + threadIdx.x;
    if (i >= n4) return;
    float4 v = *(const float4*)(x + (size_t)i * 4);
    __nv_bfloat16 h0 = __float2bfloat16(v.x), h1 = __float2bfloat16(v.y);
    __nv_bfloat16 h2 = __float2bfloat16(v.z), h3 = __float2bfloat16(v.w);
    __nv_bfloat16 l0 = __float2bfloat16(v.x - __bfloat162float(h0));
    __nv_bfloat16 l1 = __float2bfloat16(v.y - __bfloat162float(h1));
    __nv_bfloat16 l2 = __float2bfloat16(v.z - __bfloat162float(h2));
    __nv_bfloat16 l3 = __float2bfloat16(v.w - __bfloat162float(h3));
    *(__nv_bfloat162*)(hi + (size_t)i * 4)     = __nv_bfloat162(h0, h1);
    *(__nv_bfloat162*)(hi + (size_t)i * 4 + 2) = __nv_bfloat162(h2, h3);
    *(__nv_bfloat162*)(lo + (size_t)i * 4)     = __nv_bfloat162(l0, l1);
    *(__nv_bfloat162*)(lo + (size_t)i * 4 + 2) = __nv_bfloat162(l2, l3);
}

// ============================================================================
// HMMA GEMM: C[M,N] = A[M,K] * W[N,K]^T via split-bf16 3-term
// (AhBh + AhBl + AlBh). 128x128 tile, BK=32, 256 thr (8 warps, 2x4, 64x32
// warp tiles). cp.async double buffer; smem rows padded to 80B (conflict-free
// ldmatrix: 80r mod 128 covers all 16B slots).
// ============================================================================
#define LDB   80           // smem row stride, bytes (40 bf16)
#define TILEB (128 * LDB)  // 10240 B per operand tile

#define PREFETCH(buf, Ap, Bp, kcv) do { \
    const __nv_bfloat16* _ga = (Ap) + (size_t)(bm + lrow) * K + (kcv) * 32 + lch * 8; \
    const __nv_bfloat16* _gb = (Bp) + (size_t)(bn + lrow) * K + (kcv) * 32 + lch * 8; \
    uint32_t _sa = sbase + (buf) * 2 * TILEB + lrow * LDB + lch * 16; \
    uint32_t _sb = _sa + TILEB; \
    cp16(_sa, _ga);            cp16(_sa + 64 * LDB, _ga + (size_t)64 * K); \
    cp16(_sb, _gb);            cp16(_sb + 64 * LDB, _gb + (size_t)64 * K); \
    CP_COMMIT(); \
} while (0)

__global__ __launch_bounds__(256) void gemm_bf16_kernel(
    const __nv_bfloat16* __restrict__ Ahi, const __nv_bfloat16* __restrict__ Alo,
    const __nv_bfloat16* __restrict__ Bhi, const __nv_bfloat16* __restrict__ Blo,
    float* __restrict__ C, int M, int N, int K)
{
    __shared__ char sm[4 * TILEB];   // [buf][A|B]
    const uint32_t sbase = smem_u32(sm);
    const int tid = threadIdx.x;
    const int lane = tid & 31, w = tid >> 5;
    const int wm = (w >> 2) * 64, wn = (w & 3) * 32;
    const int bm = blockIdx.y * 128, bn = blockIdx.x * 128;
    const int lrow = tid >> 2, lch = tid & 3;     // loader: row 0..63, 16B chunk
    const int lmr = lane & 15, lmc = lane >> 4;   // ldmatrix lane mapping

    float acc[4][4][4];
#pragma unroll
    for (int a = 0; a < 4; a++)
#pragma unroll
        for (int b = 0; b < 4; b++)
#pragma unroll
            for (int c = 0; c < 4; c++) acc[a][b][c] = 0.f;

    const int nch = K >> 5;
    const int nIter = 3 * nch;
    const __nv_bfloat16 *Ap = Ahi, *Bp = Bhi;

    PREFETCH(0, Ap, Bp, 0);
    int kc = 1, term = 0;

    for (int it = 0; it < nIter; it++) {
        CP_WAIT0();
        __syncthreads();
        if (it + 1 < nIter) {
            if (kc == nch) {
                kc = 0; term++;
                Ap = (term == 2) ? Alo : Ahi;
                Bp = (term == 1) ? Blo : Bhi;
            }
            PREFETCH((it + 1) & 1, Ap, Bp, kc);
            kc++;
        }
        // ---- compute on buffer it&1 ----
        {
            const uint32_t sA = sbase + (it & 1) * 2 * TILEB;
            const uint32_t sB = sA + TILEB;
#pragma unroll
            for (int kk = 0; kk < 2; kk++) {
                uint32_t bfr[2][4];
#pragma unroll
                for (int nh = 0; nh < 2; nh++)
                    ldmx4(bfr[nh], sB + (wn + nh * 16 + lmr) * LDB + (kk * 2 + lmc) * 16);
#pragma unroll
                for (int mi = 0; mi < 4; mi++) {
                    uint32_t afr[4];
                    ldmx4(afr, sA + (wm + mi * 16 + lmr) * LDB + (kk * 2 + lmc) * 16);
#pragma unroll
                    for (int nh = 0; nh < 2; nh++) {
                        mma16816(acc[mi][nh * 2 + 0], afr, bfr[nh][0], bfr[nh][2]);
                        mma16816(acc[mi][nh * 2 + 1], afr, bfr[nh][1], bfr[nh][3]);
                    }
                }
            }
        }
        __syncthreads();
    }

    // ---- epilogue: float2 stores (32B sectors per 4-lane group) ----
    const int er = lane >> 2, ec = (lane & 3) * 2;
#pragma unroll
    for (int mi = 0; mi < 4; mi++)
#pragma unroll
        for (int ni = 0; ni < 4; ni++) {
            size_t row = (size_t)(bm + wm + mi * 16 + er);
            size_t col = (size_t)(bn + wn + ni * 8 + ec);
            *(float2*)&C[row * N + col]       = make_float2(acc[mi][ni][0], acc[mi][ni][1]);
            *(float2*)&C[(row + 8) * N + col] = make_float2(acc[mi][ni][2], acc[mi][ni][3]);
        }
}

// ============================================================================
// RoPE (in place), fp32 only; folds attention scale into Q.
// ============================================================================
__global__ void rope_kernel(float* __restrict__ x, int nheads, float scale)
{
    int idx = blockIdx.x * blockDim.x + threadIdx.x;
    int total = B_ * S_ * nheads * 32;
    if (idx >= total) return;
    int d = idx & 31;
    int r = idx >> 5;
    int h = r % nheads; r /= nheads;
    int s = r % S_;
    int b = r / S_;

    float inv = exp2f((float)d * -0.41524101186f);
    float fr = (float)s * inv;
    float c, sn;
    sincosf(fr, &sn, &c);

    size_t base = (((size_t)b * S_ + s) * nheads + h) * HD_;
    float x0 = x[base + d], x1 = x[base + d + 32];
    x[base + d]      = (x0 * c - x1 * sn) * scale;
    x[base + d + 32] = (x1 * c + x0 * sn) * scale;
}

// ============================================================================
// Flash attention (causal, GQA), fp32, FFMA2 inner loops (unchanged from R2).
// ============================================================================
__global__ __launch_bounds__(256, 2) void attn_kernel()
{
    extern __shared__ float smf[];
    float* Qs = smf;
    float* Ks = smf + 64 * 64;
    float* Vs = smf + 2 * 64 * 64;
    float* Ps = smf + 3 * 64 * 64;

    const int qt = (S_ / 64 - 1) - blockIdx.x;
    const int h = blockIdx.y, b = blockIdx.z;
    const int hkv = h >> 2;
    const int tid = threadIdx.x;
    const int ty = tid >> 4, tx = tid & 15;
    const int q0 = qt * 64;

    const int lr = tid >> 2;
    const int lf = tid & 3;
    const int ksw = (lr >> 2) & 15;

    {
        const float* qp = g_q + (((size_t)b * S_ + q0 + lr) * NH_ + h) * HD_;
#pragma unroll
        for (int rep = 0; rep < 4; rep++) {
            int f = lf + rep * 4;
            *(float4*)&Qs[lr * 64 + f * 4] = *(const float4*)&qp[f * 4];
        }
    }

    float m_r[4], l_r[4];
    u64 o2[4][2];
#pragma unroll
    for (int r = 0; r < 4; r++) {
        m_r[r] = -1e30f; l_r[r] = 0.f;
        o2[r][0] = 0ULL; o2[r][1] = 0ULL;
    }

    for (int j = 0; j <= qt; j++) {
        __syncthreads();
        {
            const float* kp = g_k + (((size_t)b * S_ + j * 64 + lr) * NKV_ + hkv) * HD_;
            const float* vp = g_v + (((size_t)b * S_ + j * 64 + lr) * NKV_ + hkv) * HD_;
#pragma unroll
            for (int rep = 0; rep < 4; rep++) {
                int f = lf + rep * 4;
                *(float4*)&Ks[lr * 64 + ((f ^ ksw) * 4)] = *(const float4*)&kp[f * 4];
                *(float4*)&Vs[lr * 64 + f * 4]           = *(const float4*)&vp[f * 4];
            }
        }
        __syncthreads();

        u64 s2[4][4];
#pragma unroll
        for (int r = 0; r < 4; r++)
#pragma unroll
            for (int c = 0; c < 4; c++) s2[r][c] = 0ULL;

#pragma unroll
        for (int d4 = 0; d4 < 16; d4++) {
            ulonglong2 qv[4], kv[4];
#pragma unroll
            for (int r = 0; r < 4; r++)
                qv[r] = *(const ulonglong2*)&Qs[(ty * 4 + r) * 64 + d4 * 4];
#pragma unroll
            for (int c = 0; c < 4; c++)
                kv[c] = *(const ulonglong2*)&Ks[(tx * 4 + c) * 64 + ((d4 ^ tx) & 15) * 4];
#pragma unroll
            for (int r = 0; r < 4; r++)
#pragma unroll
                for (int c = 0; c < 4; c++) {
                    s2[r][c] = ffma2(qv[r].x, kv[c].x, s2[r][c]);
                    s2[r][c] = ffma2(qv[r].y, kv[c].y, s2[r][c]);
                }
        }
        float sv[4][4];
#pragma unroll
        for (int r = 0; r < 4; r++)
#pragma unroll
            for (int c = 0; c < 4; c++) {
                float2 t = up2(s2[r][c]);
                sv[r][c] = t.x + t.y;
            }

        if (j == qt) {
#pragma unroll
            for (int r = 0; r < 4; r++)
#pragma unroll
                for (int c = 0; c < 4; c++)
                    if (tx * 4 + c > ty * 4 + r) sv[r][c] = -1e30f;
        }

#pragma unroll
        for (int r = 0; r < 4; r++) {
            float mx = fmaxf(fmaxf(sv[r][0], sv[r][1]), fmaxf(sv[r][2], sv[r][3]));
#pragma unroll
            for (int off = 1; off < 16; off <<= 1)
                mx = fmaxf(mx, __shfl_xor_sync(0xffffffffu, mx, off));
            float nm = fmaxf(m_r[r], mx);
            float alpha = __expf(m_r[r] - nm);
            float p0 = __expf(sv[r][0] - nm), p1 = __expf(sv[r][1] - nm);
            float p2 = __expf(sv[r][2] - nm), p3 = __expf(sv[r][3] - nm);
            float rs = p0 + p1 + p2 + p3;
#pragma unroll
            for (int off = 1; off < 16; off <<= 1)
                rs += __shfl_xor_sync(0xffffffffu, rs, off);
            l_r[r] = l_r[r] * alpha + rs;
            m_r[r] = nm;
            u64 a2 = pk2(alpha, alpha);
            o2[r][0] = fmul2(o2[r][0], a2);
            o2[r][1] = fmul2(o2[r][1], a2);
            *(float4*)&Ps[(ty * 4 + r) * 64 + tx * 4] = make_float4(p0, p1, p2, p3);
        }
        __syncthreads();

#pragma unroll 4
        for (int ki = 0; ki < 64; ki += 2) {
            ulonglong2 va = *(const ulonglong2*)&Vs[ki * 64 + tx * 4];
            ulonglong2 vb = *(const ulonglong2*)&Vs[(ki + 1) * 64 + tx * 4];
#pragma unroll
            for (int r = 0; r < 4; r++) {
                float2 pp = *(const float2*)&Ps[(ty * 4 + r) * 64 + ki];
                u64 pa = pk2(pp.x, pp.x), pb = pk2(pp.y, pp.y);
                o2[r][0] = ffma2(pa, va.x, o2[r][0]);
                o2[r][1] = ffma2(pa, va.y, o2[r][1]);
                o2[r][0] = ffma2(pb, vb.x, o2[r][0]);
                o2[r][1] = ffma2(pb, vb.y, o2[r][1]);
            }
        }
    }

#pragma unroll
    for (int r = 0; r < 4; r++) {
        float inv = 1.0f / l_r[r];
        float2 a = up2(o2[r][0]), bq = up2(o2[r][1]);
        size_t row = (size_t)b * S_ + (q0 + ty * 4 + r);
        *(float4*)&g_o[(row * NH_ + h) * HD_ + tx * 4] =
            make_float4(a.x * inv, a.y * inv, bq.x * inv, bq.y * inv);
    }
}

// ============================================================================
extern "C" void kernel_launch(void* const* d_in, const int* in_sizes, int n_in,
                              void* d_out, int out_size)
{
    const float* hs = (const float*)d_in[0];
    const float* Wq = (const float*)d_in[1];
    const float* Wk = (const float*)d_in[2];
    const float* Wv = (const float*)d_in[3];
    const float* Wo = (const float*)d_in[4];
    float* out = (float*)d_out;

    float *qp, *kp, *vp, *op;
    __nv_bfloat16 *hsh, *hsl, *wh, *wl, *ohh, *ohl;
    cudaGetSymbolAddress((void**)&qp, g_q);
    cudaGetSymbolAddress((void**)&kp, g_k);
    cudaGetSymbolAddress((void**)&vp, g_v);
    cudaGetSymbolAddress((void**)&op, g_o);
    cudaGetSymbolAddress((void**)&hsh, g_hs_hi);
    cudaGetSymbolAddress((void**)&hsl, g_hs_lo);
    cudaGetSymbolAddress((void**)&wh, g_w_hi);
    cudaGetSymbolAddress((void**)&wl, g_w_lo);
    cudaGetSymbolAddress((void**)&ohh, g_oh_hi);
    cudaGetSymbolAddress((void**)&ohl, g_oh_lo);

    const int M = B_ * S_;                 // 4096
    const int nHS = B_ * S_ * H_;          // 8388608
    const int nWqo = H_ * H_;              // 4194304
    const int nWkv = NKV_ * HD_ * H_;      // 1048576

    // split hidden states
    split_kernel<<<nHS / 4 / 256, 256>>>(hs, hsh, hsl, nHS / 4);

    // Q = hs @ Wq^T
    split_kernel<<<nWqo / 4 / 256, 256>>>(Wq, wh, wl, nWqo / 4);
    gemm_bf16_kernel<<<dim3(16, 32), 256>>>(hsh, hsl, wh, wl, qp, M, NH_ * HD_, H_);
    // K
    split_kernel<<<nWkv / 4 / 256, 256>>>(Wk, wh, wl, nWkv / 4);
    gemm_bf16_kernel<<<dim3(4, 32), 256>>>(hsh, hsl, wh, wl, kp, M, NKV_ * HD_, H_);
    // V
    split_kernel<<<nWkv / 4 / 256, 256>>>(Wv, wh, wl, nWkv / 4);
    gemm_bf16_kernel<<<dim3(4, 32), 256>>>(hsh, hsl, wh, wl, vp, M, NKV_ * HD_, H_);

    // RoPE (scale 1/sqrt(64) folded into Q)
    rope_kernel<<<(B_ * S_ * NH_ * 32 + 255) / 256, 256>>>(qp, NH_, 0.125f);
    rope_kernel<<<(B_ * S_ * NKV_ * 32 + 255) / 256, 256>>>(kp, NKV_, 1.0f);

    // attention
    cudaFuncSetAttribute(attn_kernel, cudaFuncAttributeMaxDynamicSharedMemorySize, 65536);
    attn_kernel<<<dim3(S_ / 64, NH_, B_), 256, 65536>>>();

    // out-proj: out = attn_out @ Wo^T
    split_kernel<<<nHS / 4 / 256, 256>>>(op, ohh, ohl, nHS / 4);
    split_kernel<<<nWqo / 4 / 256, 256>>>(Wo, wh, wl, nWqo / 4);
    gemm_bf16_kernel<<<dim3(16, 32), 256>>>(ohh, ohl, wh, wl, out, M, H_, H_);
}

// round 10
// speedup vs baseline: 1.9007x; 1.0551x over previous
#include <cuda_runtime.h>
#include <cuda_bf16.h>
#include <math.h>
#include <cstdint>

// Problem dims
#define B_   2
#define S_   2048
#define H_   2048
#define NH_  32
#define NKV_ 8
#define HD_  64

// fp32 scratch
__device__ float g_q[(size_t)B_ * S_ * NH_ * HD_];
__device__ float g_k[(size_t)B_ * S_ * NKV_ * HD_];
__device__ float g_v[(size_t)B_ * S_ * NKV_ * HD_];
__device__ float g_o[(size_t)B_ * S_ * NH_ * HD_];

// bf16 split scratch (hi/lo)
__device__ __nv_bfloat16 g_hs_hi[(size_t)B_ * S_ * H_];
__device__ __nv_bfloat16 g_hs_lo[(size_t)B_ * S_ * H_];
__device__ __nv_bfloat16 g_w_hi[(size_t)H_ * H_];
__device__ __nv_bfloat16 g_w_lo[(size_t)H_ * H_];
__device__ __nv_bfloat16 g_oh_hi[(size_t)B_ * S_ * NH_ * HD_];
__device__ __nv_bfloat16 g_oh_lo[(size_t)B_ * S_ * NH_ * HD_];

typedef unsigned long long u64;

// ---- packed f32x2 helpers (used by attention) ----
__device__ __forceinline__ u64 ffma2(u64 a, u64 b, u64 c) {
    u64 d;
    asm("fma.rn.f32x2 %0, %1, %2, %3;" : "=l"(d) : "l"(a), "l"(b), "l"(c));
    return d;
}
__device__ __forceinline__ u64 fmul2(u64 a, u64 b) {
    u64 d;
    asm("mul.rn.f32x2 %0, %1, %2;" : "=l"(d) : "l"(a), "l"(b));
    return d;
}
__device__ __forceinline__ u64 pk2(float x, float y) {
    u64 r;
    asm("mov.b64 %0, {%1, %2};" : "=l"(r) : "f"(x), "f"(y));
    return r;
}
__device__ __forceinline__ float2 up2(u64 v) {
    float2 f;
    asm("mov.b64 {%0, %1}, %2;" : "=f"(f.x), "=f"(f.y) : "l"(v));
    return f;
}

// ---- mma.sync / ldmatrix / cp.async helpers ----
__device__ __forceinline__ uint32_t smem_u32(const void* p) {
    uint32_t a;
    asm("{ .reg .u64 t; cvta.to.shared.u64 t, %1; cvt.u32.u64 %0, t; }" : "=r"(a) : "l"(p));
    return a;
}
__device__ __forceinline__ void ldmx4(uint32_t* r, uint32_t addr) {
    asm volatile("ldmatrix.sync.aligned.m8n8.x4.shared.b16 {%0,%1,%2,%3}, [%4];"
                 : "=r"(r[0]), "=r"(r[1]), "=r"(r[2]), "=r"(r[3]) : "r"(addr));
}
__device__ __forceinline__ void mma16816(float* c, const uint32_t* a, uint32_t b0, uint32_t b1) {
    asm volatile("mma.sync.aligned.m16n8k16.row.col.f32.bf16.bf16.f32 "
                 "{%0,%1,%2,%3}, {%4,%5,%6,%7}, {%8,%9}, {%0,%1,%2,%3};"
                 : "+f"(c[0]), "+f"(c[1]), "+f"(c[2]), "+f"(c[3])
                 : "r"(a[0]), "r"(a[1]), "r"(a[2]), "r"(a[3]), "r"(b0), "r"(b1));
}
__device__ __forceinline__ void cp16(uint32_t s, const void* g) {
    asm volatile("cp.async.ca.shared.global [%0], [%1], 16;" :: "r"(s), "l"(g));
}
#define CP_COMMIT() asm volatile("cp.async.commit_group;" ::: "memory")
#define CP_WAIT0()  asm volatile("cp.async.wait_group 0;" ::: "memory")

// ============================================================================
// split: fp32 -> bf16 hi + bf16 lo (x ~= hi + lo)
// ============================================================================
__global__ void split_kernel(const float* __restrict__ x,
                             __nv_bfloat16* __restrict__ hi,
                             __nv_bfloat16* __restrict__ lo, int n4)
{
    int i = blockIdx.x * blockDim.x + threadIdx.x;
    if (i >= n4) return;
    float4 v = *(const float4*)(x + (size_t)i * 4);
    __nv_bfloat16 h0 = __float2bfloat16(v.x), h1 = __float2bfloat16(v.y);
    __nv_bfloat16 h2 = __float2bfloat16(v.z), h3 = __float2bfloat16(v.w);
    __nv_bfloat16 l0 = __float2bfloat16(v.x - __bfloat162float(h0));
    __nv_bfloat16 l1 = __float2bfloat16(v.y - __bfloat162float(h1));
    __nv_bfloat16 l2 = __float2bfloat16(v.z - __bfloat162float(h2));
    __nv_bfloat16 l3 = __float2bfloat16(v.w - __bfloat162float(h3));
    *(__nv_bfloat162*)(hi + (size_t)i * 4)     = __nv_bfloat162(h0, h1);
    *(__nv_bfloat162*)(hi + (size_t)i * 4 + 2) = __nv_bfloat162(h2, h3);
    *(__nv_bfloat162*)(lo + (size_t)i * 4)     = __nv_bfloat162(l0, l1);
    *(__nv_bfloat162*)(lo + (size_t)i * 4 + 2) = __nv_bfloat162(l2, l3);
}

// ============================================================================
// HMMA GEMM: C[M,N] = A[M,K] * W[N,K]^T via split-bf16 3-term, SINGLE PASS:
// Ah, Al, Bh, Bl tiles all resident in smem per K-chunk; 3 MMA terms issued
// from the same tiles (3x less smem-fill traffic + 3x fewer barriers than the
// per-term-pass version). 128x128 tile, BK=32, 256 thr (8 warps, 2x4).
// cp.async double buffer; rows padded to 80B (conflict-free ldmatrix).
// ============================================================================
#define LDB   80            // smem row stride, bytes (40 bf16)
#define TILEB (128 * LDB)   // 10240 B per operand tile
#define STAGEB (4 * TILEB)  // Ah, Al, Bh, Bl
#define GEMM_SMEM (2 * STAGEB)  // 81920

// loader: thread -> (row = tid>>1, 32B half = tid&1) per 128-row tile
#define PREFETCH(buf, kcv) do { \
    size_t goff = (size_t)(kcv) * 32 + lc2 * 8; \
    uint32_t sro = (buf) * STAGEB + lrow * LDB + lc2 * 16; \
    const __nv_bfloat16* _ga = Ahi + (size_t)(bm + lrow) * K + goff; \
    const __nv_bfloat16* _gl = Alo + (size_t)(bm + lrow) * K + goff; \
    const __nv_bfloat16* _gb = Bhi + (size_t)(bn + lrow) * K + goff; \
    const __nv_bfloat16* _gc = Blo + (size_t)(bn + lrow) * K + goff; \
    cp16(sbase + sro,             _ga); cp16(sbase + sro + 16,             _ga + 8); \
    cp16(sbase + sro + TILEB,     _gl); cp16(sbase + sro + TILEB + 16,     _gl + 8); \
    cp16(sbase + sro + 2 * TILEB, _gb); cp16(sbase + sro + 2 * TILEB + 16, _gb + 8); \
    cp16(sbase + sro + 3 * TILEB, _gc); cp16(sbase + sro + 3 * TILEB + 16, _gc + 8); \
    CP_COMMIT(); \
} while (0)

__global__ __launch_bounds__(256, 2) void gemm_bf16_kernel(
    const __nv_bfloat16* __restrict__ Ahi, const __nv_bfloat16* __restrict__ Alo,
    const __nv_bfloat16* __restrict__ Bhi, const __nv_bfloat16* __restrict__ Blo,
    float* __restrict__ C, int M, int N, int K)
{
    extern __shared__ char smemg[];
    const uint32_t sbase = smem_u32(smemg);
    const int tid = threadIdx.x;
    const int lane = tid & 31, w = tid >> 5;
    const int wm = (w >> 2) * 64, wn = (w & 3) * 32;
    const int bm = blockIdx.y * 128, bn = blockIdx.x * 128;
    const int lrow = tid >> 1, lc2 = (tid & 1) * 2;  // loader: row, 32B half
    const int lmr = lane & 15, lmc = lane >> 4;      // ldmatrix lane mapping

    float acc[4][4][4];
#pragma unroll
    for (int a = 0; a < 4; a++)
#pragma unroll
        for (int b = 0; b < 4; b++)
#pragma unroll
            for (int c = 0; c < 4; c++) acc[a][b][c] = 0.f;

    const int nch = K >> 5;
    PREFETCH(0, 0);

    for (int it = 0; it < nch; it++) {
        CP_WAIT0();
        __syncthreads();
        if (it + 1 < nch) PREFETCH((it + 1) & 1, it + 1);

        const uint32_t sAh = sbase + (it & 1) * STAGEB;
        const uint32_t sAl = sAh + TILEB;
        const uint32_t sBh = sAh + 2 * TILEB;
        const uint32_t sBl = sAh + 3 * TILEB;
#pragma unroll
        for (int kk = 0; kk < 2; kk++) {
            uint32_t bh[2][4], bl[2][4];
#pragma unroll
            for (int nh = 0; nh < 2; nh++) {
                uint32_t ro = (wn + nh * 16 + lmr) * LDB + (kk * 2 + lmc) * 16;
                ldmx4(bh[nh], sBh + ro);
                ldmx4(bl[nh], sBl + ro);
            }
#pragma unroll
            for (int mi = 0; mi < 4; mi++) {
                uint32_t ah[4], al[4];
                uint32_t ro = (wm + mi * 16 + lmr) * LDB + (kk * 2 + lmc) * 16;
                ldmx4(ah, sAh + ro);
                ldmx4(al, sAl + ro);
#pragma unroll
                for (int nh = 0; nh < 2; nh++) {
                    mma16816(acc[mi][nh * 2 + 0], ah, bh[nh][0], bh[nh][2]);
                    mma16816(acc[mi][nh * 2 + 1], ah, bh[nh][1], bh[nh][3]);
                    mma16816(acc[mi][nh * 2 + 0], ah, bl[nh][0], bl[nh][2]);
                    mma16816(acc[mi][nh * 2 + 1], ah, bl[nh][1], bl[nh][3]);
                    mma16816(acc[mi][nh * 2 + 0], al, bh[nh][0], bh[nh][2]);
                    mma16816(acc[mi][nh * 2 + 1], al, bh[nh][1], bh[nh][3]);
                }
            }
        }
        __syncthreads();
    }

    // ---- epilogue: float2 stores (32B sectors per 4-lane group) ----
    const int er = lane >> 2, ec = (lane & 3) * 2;
#pragma unroll
    for (int mi = 0; mi < 4; mi++)
#pragma unroll
        for (int ni = 0; ni < 4; ni++) {
            size_t row = (size_t)(bm + wm + mi * 16 + er);
            size_t col = (size_t)(bn + wn + ni * 8 + ec);
            *(float2*)&C[row * N + col]       = make_float2(acc[mi][ni][0], acc[mi][ni][1]);
            *(float2*)&C[(row + 8) * N + col] = make_float2(acc[mi][ni][2], acc[mi][ni][3]);
        }
}

// ============================================================================
// RoPE (in place), fp32 only; folds attention scale into Q.
// ============================================================================
__global__ void rope_kernel(float* __restrict__ x, int nheads, float scale)
{
    int idx = blockIdx.x * blockDim.x + threadIdx.x;
    int total = B_ * S_ * nheads * 32;
    if (idx >= total) return;
    int d = idx & 31;
    int r = idx >> 5;
    int h = r % nheads; r /= nheads;
    int s = r % S_;
    int b = r / S_;

    float inv = exp2f((float)d * -0.41524101186f);
    float fr = (float)s * inv;
    float c, sn;
    sincosf(fr, &sn, &c);

    size_t base = (((size_t)b * S_ + s) * nheads + h) * HD_;
    float x0 = x[base + d], x1 = x[base + d + 32];
    x[base + d]      = (x0 * c - x1 * sn) * scale;
    x[base + d + 32] = (x1 * c + x0 * sn) * scale;
}

// ============================================================================
// Flash attention (causal, GQA), fp32, FFMA2 inner loops (unchanged).
// ============================================================================
__global__ __launch_bounds__(256, 2) void attn_kernel()
{
    extern __shared__ float smf[];
    float* Qs = smf;
    float* Ks = smf + 64 * 64;
    float* Vs = smf + 2 * 64 * 64;
    float* Ps = smf + 3 * 64 * 64;

    const int qt = (S_ / 64 - 1) - blockIdx.x;
    const int h = blockIdx.y, b = blockIdx.z;
    const int hkv = h >> 2;
    const int tid = threadIdx.x;
    const int ty = tid >> 4, tx = tid & 15;
    const int q0 = qt * 64;

    const int lr = tid >> 2;
    const int lf = tid & 3;
    const int ksw = (lr >> 2) & 15;

    {
        const float* qp = g_q + (((size_t)b * S_ + q0 + lr) * NH_ + h) * HD_;
#pragma unroll
        for (int rep = 0; rep < 4; rep++) {
            int f = lf + rep * 4;
            *(float4*)&Qs[lr * 64 + f * 4] = *(const float4*)&qp[f * 4];
        }
    }

    float m_r[4], l_r[4];
    u64 o2[4][2];
#pragma unroll
    for (int r = 0; r < 4; r++) {
        m_r[r] = -1e30f; l_r[r] = 0.f;
        o2[r][0] = 0ULL; o2[r][1] = 0ULL;
    }

    for (int j = 0; j <= qt; j++) {
        __syncthreads();
        {
            const float* kp = g_k + (((size_t)b * S_ + j * 64 + lr) * NKV_ + hkv) * HD_;
            const float* vp = g_v + (((size_t)b * S_ + j * 64 + lr) * NKV_ + hkv) * HD_;
#pragma unroll
            for (int rep = 0; rep < 4; rep++) {
                int f = lf + rep * 4;
                *(float4*)&Ks[lr * 64 + ((f ^ ksw) * 4)] = *(const float4*)&kp[f * 4];
                *(float4*)&Vs[lr * 64 + f * 4]           = *(const float4*)&vp[f * 4];
            }
        }
        __syncthreads();

        u64 s2[4][4];
#pragma unroll
        for (int r = 0; r < 4; r++)
#pragma unroll
            for (int c = 0; c < 4; c++) s2[r][c] = 0ULL;

#pragma unroll
        for (int d4 = 0; d4 < 16; d4++) {
            ulonglong2 qv[4], kv[4];
#pragma unroll
            for (int r = 0; r < 4; r++)
                qv[r] = *(const ulonglong2*)&Qs[(ty * 4 + r) * 64 + d4 * 4];
#pragma unroll
            for (int c = 0; c < 4; c++)
                kv[c] = *(const ulonglong2*)&Ks[(tx * 4 + c) * 64 + ((d4 ^ tx) & 15) * 4];
#pragma unroll
            for (int r = 0; r < 4; r++)
#pragma unroll
                for (int c = 0; c < 4; c++) {
                    s2[r][c] = ffma2(qv[r].x, kv[c].x, s2[r][c]);
                    s2[r][c] = ffma2(qv[r].y, kv[c].y, s2[r][c]);
                }
        }
        float sv[4][4];
#pragma unroll
        for (int r = 0; r < 4; r++)
#pragma unroll
            for (int c = 0; c < 4; c++) {
                float2 t = up2(s2[r][c]);
                sv[r][c] = t.x + t.y;
            }

        if (j == qt) {
#pragma unroll
            for (int r = 0; r < 4; r++)
#pragma unroll
                for (int c = 0; c < 4; c++)
                    if (tx * 4 + c > ty * 4 + r) sv[r][c] = -1e30f;
        }

#pragma unroll
        for (int r = 0; r < 4; r++) {
            float mx = fmaxf(fmaxf(sv[r][0], sv[r][1]), fmaxf(sv[r][2], sv[r][3]));
#pragma unroll
            for (int off = 1; off < 16; off <<= 1)
                mx = fmaxf(mx, __shfl_xor_sync(0xffffffffu, mx, off));
            float nm = fmaxf(m_r[r], mx);
            float alpha = __expf(m_r[r] - nm);
            float p0 = __expf(sv[r][0] - nm), p1 = __expf(sv[r][1] - nm);
            float p2 = __expf(sv[r][2] - nm), p3 = __expf(sv[r][3] - nm);
            float rs = p0 + p1 + p2 + p3;
#pragma unroll
            for (int off = 1; off < 16; off <<= 1)
                rs += __shfl_xor_sync(0xffffffffu, rs, off);
            l_r[r] = l_r[r] * alpha + rs;
            m_r[r] = nm;
            u64 a2 = pk2(alpha, alpha);
            o2[r][0] = fmul2(o2[r][0], a2);
            o2[r][1] = fmul2(o2[r][1], a2);
            *(float4*)&Ps[(ty * 4 + r) * 64 + tx * 4] = make_float4(p0, p1, p2, p3);
        }
        __syncthreads();

#pragma unroll 4
        for (int ki = 0; ki < 64; ki += 2) {
            ulonglong2 va = *(const ulonglong2*)&Vs[ki * 64 + tx * 4];
            ulonglong2 vb = *(const ulonglong2*)&Vs[(ki + 1) * 64 + tx * 4];
#pragma unroll
            for (int r = 0; r < 4; r++) {
                float2 pp = *(const float2*)&Ps[(ty * 4 + r) * 64 + ki];
                u64 pa = pk2(pp.x, pp.x), pb = pk2(pp.y, pp.y);
                o2[r][0] = ffma2(pa, va.x, o2[r][0]);
                o2[r][1] = ffma2(pa, va.y, o2[r][1]);
                o2[r][0] = ffma2(pb, vb.x, o2[r][0]);
                o2[r][1] = ffma2(pb, vb.y, o2[r][1]);
            }
        }
    }

#pragma unroll
    for (int r = 0; r < 4; r++) {
        float inv = 1.0f / l_r[r];
        float2 a = up2(o2[r][0]), bq = up2(o2[r][1]);
        size_t row = (size_t)b * S_ + (q0 + ty * 4 + r);
        *(float4*)&g_o[(row * NH_ + h) * HD_ + tx * 4] =
            make_float4(a.x * inv, a.y * inv, bq.x * inv, bq.y * inv);
    }
}

// ============================================================================
extern "C" void kernel_launch(void* const* d_in, const int* in_sizes, int n_in,
                              void* d_out, int out_size)
{
    const float* hs = (const float*)d_in[0];
    const float* Wq = (const float*)d_in[1];
    const float* Wk = (const float*)d_in[2];
    const float* Wv = (const float*)d_in[3];
    const float* Wo = (const float*)d_in[4];
    float* out = (float*)d_out;

    float *qp, *kp, *vp, *op;
    __nv_bfloat16 *hsh, *hsl, *wh, *wl, *ohh, *ohl;
    cudaGetSymbolAddress((void**)&qp, g_q);
    cudaGetSymbolAddress((void**)&kp, g_k);
    cudaGetSymbolAddress((void**)&vp, g_v);
    cudaGetSymbolAddress((void**)&op, g_o);
    cudaGetSymbolAddress((void**)&hsh, g_hs_hi);
    cudaGetSymbolAddress((void**)&hsl, g_hs_lo);
    cudaGetSymbolAddress((void**)&wh, g_w_hi);
    cudaGetSymbolAddress((void**)&wl, g_w_lo);
    cudaGetSymbolAddress((void**)&ohh, g_oh_hi);
    cudaGetSymbolAddress((void**)&ohl, g_oh_lo);

    const int M = B_ * S_;                 // 4096
    const int nHS = B_ * S_ * H_;          // 8388608
    const int nWqo = H_ * H_;              // 4194304
    const int nWkv = NKV_ * HD_ * H_;      // 1048576

    cudaFuncSetAttribute(gemm_bf16_kernel, cudaFuncAttributeMaxDynamicSharedMemorySize, GEMM_SMEM);

    // split hidden states
    split_kernel<<<nHS / 4 / 256, 256>>>(hs, hsh, hsl, nHS / 4);

    // Q = hs @ Wq^T
    split_kernel<<<nWqo / 4 / 256, 256>>>(Wq, wh, wl, nWqo / 4);
    gemm_bf16_kernel<<<dim3(16, 32), 256, GEMM_SMEM>>>(hsh, hsl, wh, wl, qp, M, NH_ * HD_, H_);
    // K
    split_kernel<<<nWkv / 4 / 256, 256>>>(Wk, wh, wl, nWkv / 4);
    gemm_bf16_kernel<<<dim3(4, 32), 256, GEMM_SMEM>>>(hsh, hsl, wh, wl, kp, M, NKV_ * HD_, H_);
    // V
    split_kernel<<<nWkv / 4 / 256, 256>>>(Wv, wh, wl, nWkv / 4);
    gemm_bf16_kernel<<<dim3(4, 32), 256, GEMM_SMEM>>>(hsh, hsl, wh, wl, vp, M, NKV_ * HD_, H_);

    // RoPE (scale 1/sqrt(64) folded into Q)
    rope_kernel<<<(B_ * S_ * NH_ * 32 + 255) / 256, 256>>>(qp, NH_, 0.125f);
    rope_kernel<<<(B_ * S_ * NKV_ * 32 + 255) / 256, 256>>>(kp, NKV_, 1.0f);

    // attention
    cudaFuncSetAttribute(attn_kernel, cudaFuncAttributeMaxDynamicSharedMemorySize, 65536);
    attn_kernel<<<dim3(S_ / 64, NH_, B_), 256, 65536>>>();

    // out-proj: out = attn_out @ Wo^T
    split_kernel<<<nHS / 4 / 256, 256>>>(op, ohh, ohl, nHS / 4);
    split_kernel<<<nWqo / 4 / 256, 256>>>(Wo, wh, wl, nWqo / 4);
    gemm_bf16_kernel<<<dim3(16, 32), 256, GEMM_SMEM>>>(ohh, ohl, wh, wl, out, M, H_, H_);
}

// round 11
// speedup vs baseline: 2.8478x; 1.4983x over previous
#include <cuda_runtime.h>
#include <cuda_bf16.h>
#include <math.h>
#include <cstdint>

// Problem dims
#define B_   2
#define S_   2048
#define H_   2048
#define NH_  32
#define NKV_ 8
#define HD_  64

// fp32 scratch
__device__ float g_q[(size_t)B_ * S_ * NH_ * HD_];
__device__ float g_k[(size_t)B_ * S_ * NKV_ * HD_];
__device__ float g_v[(size_t)B_ * S_ * NKV_ * HD_];
__device__ float g_o[(size_t)B_ * S_ * NH_ * HD_];

// bf16 split scratch for GEMMs
__device__ __nv_bfloat16 g_hs_hi[(size_t)B_ * S_ * H_];
__device__ __nv_bfloat16 g_hs_lo[(size_t)B_ * S_ * H_];
__device__ __nv_bfloat16 g_w_hi[(size_t)H_ * H_];
__device__ __nv_bfloat16 g_w_lo[(size_t)H_ * H_];
__device__ __nv_bfloat16 g_oh_hi[(size_t)B_ * S_ * NH_ * HD_];
__device__ __nv_bfloat16 g_oh_lo[(size_t)B_ * S_ * NH_ * HD_];

// bf16 split attention operands, head-major [B, heads, S, HD]
__device__ __nv_bfloat16 g_qh[(size_t)B_ * NH_ * S_ * HD_];
__device__ __nv_bfloat16 g_ql[(size_t)B_ * NH_ * S_ * HD_];
__device__ __nv_bfloat16 g_kh2[(size_t)B_ * NKV_ * S_ * HD_];
__device__ __nv_bfloat16 g_kl2[(size_t)B_ * NKV_ * S_ * HD_];
__device__ __nv_bfloat16 g_vh2[(size_t)B_ * NKV_ * S_ * HD_];
__device__ __nv_bfloat16 g_vl2[(size_t)B_ * NKV_ * S_ * HD_];

typedef unsigned long long u64;

// ---- mma.sync / ldmatrix / cp.async helpers ----
__device__ __forceinline__ uint32_t smem_u32(const void* p) {
    uint32_t a;
    asm("{ .reg .u64 t; cvta.to.shared.u64 t, %1; cvt.u32.u64 %0, t; }" : "=r"(a) : "l"(p));
    return a;
}
__device__ __forceinline__ void ldmx4(uint32_t* r, uint32_t addr) {
    asm volatile("ldmatrix.sync.aligned.m8n8.x4.shared.b16 {%0,%1,%2,%3}, [%4];"
                 : "=r"(r[0]), "=r"(r[1]), "=r"(r[2]), "=r"(r[3]) : "r"(addr));
}
__device__ __forceinline__ void ldmx4t(uint32_t* r, uint32_t addr) {
    asm volatile("ldmatrix.sync.aligned.m8n8.x4.trans.shared.b16 {%0,%1,%2,%3}, [%4];"
                 : "=r"(r[0]), "=r"(r[1]), "=r"(r[2]), "=r"(r[3]) : "r"(addr));
}
__device__ __forceinline__ void mma16816(float* c, const uint32_t* a, uint32_t b0, uint32_t b1) {
    asm volatile("mma.sync.aligned.m16n8k16.row.col.f32.bf16.bf16.f32 "
                 "{%0,%1,%2,%3}, {%4,%5,%6,%7}, {%8,%9}, {%0,%1,%2,%3};"
                 : "+f"(c[0]), "+f"(c[1]), "+f"(c[2]), "+f"(c[3])
                 : "r"(a[0]), "r"(a[1]), "r"(a[2]), "r"(a[3]), "r"(b0), "r"(b1));
}
__device__ __forceinline__ void cp16(uint32_t s, const void* g) {
    asm volatile("cp.async.ca.shared.global [%0], [%1], 16;" :: "r"(s), "l"(g));
}
#define CP_COMMIT() asm volatile("cp.async.commit_group;" ::: "memory")
#define CP_WAIT0()  asm volatile("cp.async.wait_group 0;" ::: "memory")

__device__ __forceinline__ uint32_t pkbf(float x, float y) {
    __nv_bfloat162 t(__float2bfloat16(x), __float2bfloat16(y));
    return *(uint32_t*)&t;
}
__device__ __forceinline__ void splitpk(float x, float y, uint32_t& hi, uint32_t& lo) {
    float hx = __bfloat162float(__float2bfloat16(x));
    float hy = __bfloat162float(__float2bfloat16(y));
    hi = pkbf(hx, hy);
    lo = pkbf(x - hx, y - hy);
}

// ============================================================================
// split: fp32 -> bf16 hi + lo (same layout)
// ============================================================================
__global__ void split_kernel(const float* __restrict__ x,
                             __nv_bfloat16* __restrict__ hi,
                             __nv_bfloat16* __restrict__ lo, int n4)
{
    int i = blockIdx.x * blockDim.x + threadIdx.x;
    if (i >= n4) return;
    float4 v = *(const float4*)(x + (size_t)i * 4);
    float h0 = __bfloat162float(__float2bfloat16(v.x));
    float h1 = __bfloat162float(__float2bfloat16(v.y));
    float h2 = __bfloat162float(__float2bfloat16(v.z));
    float h3 = __bfloat162float(__float2bfloat16(v.w));
    *(uint32_t*)(hi + (size_t)i * 4)     = pkbf(h0, h1);
    *(uint32_t*)(hi + (size_t)i * 4 + 2) = pkbf(h2, h3);
    *(uint32_t*)(lo + (size_t)i * 4)     = pkbf(v.x - h0, v.y - h1);
    *(uint32_t*)(lo + (size_t)i * 4 + 2) = pkbf(v.z - h2, v.w - h3);
}

// ============================================================================
// HMMA GEMM (unchanged from R10): split-bf16 3-term single pass.
// ============================================================================
#define LDB   80
#define TILEB (128 * LDB)
#define STAGEB (4 * TILEB)
#define GEMM_SMEM (2 * STAGEB)

#define PREFETCH(buf, kcv) do { \
    size_t goff = (size_t)(kcv) * 32 + lc2 * 8; \
    uint32_t sro = (buf) * STAGEB + lrow * LDB + lc2 * 16; \
    const __nv_bfloat16* _ga = Ahi + (size_t)(bm + lrow) * K + goff; \
    const __nv_bfloat16* _gl = Alo + (size_t)(bm + lrow) * K + goff; \
    const __nv_bfloat16* _gb = Bhi + (size_t)(bn + lrow) * K + goff; \
    const __nv_bfloat16* _gc = Blo + (size_t)(bn + lrow) * K + goff; \
    cp16(sbase + sro,             _ga); cp16(sbase + sro + 16,             _ga + 8); \
    cp16(sbase + sro + TILEB,     _gl); cp16(sbase + sro + TILEB + 16,     _gl + 8); \
    cp16(sbase + sro + 2 * TILEB, _gb); cp16(sbase + sro + 2 * TILEB + 16, _gb + 8); \
    cp16(sbase + sro + 3 * TILEB, _gc); cp16(sbase + sro + 3 * TILEB + 16, _gc + 8); \
    CP_COMMIT(); \
} while (0)

__global__ __launch_bounds__(256, 2) void gemm_bf16_kernel(
    const __nv_bfloat16* __restrict__ Ahi, const __nv_bfloat16* __restrict__ Alo,
    const __nv_bfloat16* __restrict__ Bhi, const __nv_bfloat16* __restrict__ Blo,
    float* __restrict__ C, int M, int N, int K)
{
    extern __shared__ char smemg[];
    const uint32_t sbase = smem_u32(smemg);
    const int tid = threadIdx.x;
    const int lane = tid & 31, w = tid >> 5;
    const int wm = (w >> 2) * 64, wn = (w & 3) * 32;
    const int bm = blockIdx.y * 128, bn = blockIdx.x * 128;
    const int lrow = tid >> 1, lc2 = (tid & 1) * 2;
    const int lmr = lane & 15, lmc = lane >> 4;

    float acc[4][4][4];
#pragma unroll
    for (int a = 0; a < 4; a++)
#pragma unroll
        for (int b = 0; b < 4; b++)
#pragma unroll
            for (int c = 0; c < 4; c++) acc[a][b][c] = 0.f;

    const int nch = K >> 5;
    PREFETCH(0, 0);

    for (int it = 0; it < nch; it++) {
        CP_WAIT0();
        __syncthreads();
        if (it + 1 < nch) PREFETCH((it + 1) & 1, it + 1);

        const uint32_t sAh = sbase + (it & 1) * STAGEB;
        const uint32_t sAl = sAh + TILEB;
        const uint32_t sBh = sAh + 2 * TILEB;
        const uint32_t sBl = sAh + 3 * TILEB;
#pragma unroll
        for (int kk = 0; kk < 2; kk++) {
            uint32_t bh[2][4], bl[2][4];
#pragma unroll
            for (int nh = 0; nh < 2; nh++) {
                uint32_t ro = (wn + nh * 16 + lmr) * LDB + (kk * 2 + lmc) * 16;
                ldmx4(bh[nh], sBh + ro);
                ldmx4(bl[nh], sBl + ro);
            }
#pragma unroll
            for (int mi = 0; mi < 4; mi++) {
                uint32_t ah[4], al[4];
                uint32_t ro = (wm + mi * 16 + lmr) * LDB + (kk * 2 + lmc) * 16;
                ldmx4(ah, sAh + ro);
                ldmx4(al, sAl + ro);
#pragma unroll
                for (int nh = 0; nh < 2; nh++) {
                    mma16816(acc[mi][nh * 2 + 0], ah, bh[nh][0], bh[nh][2]);
                    mma16816(acc[mi][nh * 2 + 1], ah, bh[nh][1], bh[nh][3]);
                    mma16816(acc[mi][nh * 2 + 0], ah, bl[nh][0], bl[nh][2]);
                    mma16816(acc[mi][nh * 2 + 1], ah, bl[nh][1], bl[nh][3]);
                    mma16816(acc[mi][nh * 2 + 0], al, bh[nh][0], bh[nh][2]);
                    mma16816(acc[mi][nh * 2 + 1], al, bh[nh][1], bh[nh][3]);
                }
            }
        }
        __syncthreads();
    }

    const int er = lane >> 2, ec = (lane & 3) * 2;
#pragma unroll
    for (int mi = 0; mi < 4; mi++)
#pragma unroll
        for (int ni = 0; ni < 4; ni++) {
            size_t row = (size_t)(bm + wm + mi * 16 + er);
            size_t col = (size_t)(bn + wn + ni * 8 + ec);
            *(float2*)&C[row * N + col]       = make_float2(acc[mi][ni][0], acc[mi][ni][1]);
            *(float2*)&C[(row + 8) * N + col] = make_float2(acc[mi][ni][2], acc[mi][ni][3]);
        }
}

// ============================================================================
// RoPE + split + relayout: fp32 [B,S,nh,HD] -> bf16 hi/lo [B,nh,S,HD].
// Scale folded (Q only).
// ============================================================================
__global__ void rope_split_kernel(const float* __restrict__ x,
                                  __nv_bfloat16* __restrict__ hi,
                                  __nv_bfloat16* __restrict__ lo,
                                  int nheads, float scale)
{
    int idx = blockIdx.x * blockDim.x + threadIdx.x;
    int total = B_ * S_ * nheads * 32;
    if (idx >= total) return;
    int d = idx & 31;
    int r = idx >> 5;
    int h = r % nheads; r /= nheads;
    int s = r % S_;
    int b = r / S_;

    float inv = exp2f((float)d * -0.41524101186f);
    float fr = (float)s * inv;
    float c, sn;
    sincosf(fr, &sn, &c);

    size_t src = (((size_t)b * S_ + s) * nheads + h) * HD_;
    float x0 = x[src + d], x1 = x[src + d + 32];
    float y0 = (x0 * c - x1 * sn) * scale;
    float y1 = (x1 * c + x0 * sn) * scale;

    size_t dst = (((size_t)b * nheads + h) * S_ + s) * HD_;
    float h0 = __bfloat162float(__float2bfloat16(y0));
    float h1 = __bfloat162float(__float2bfloat16(y1));
    hi[dst + d]      = __float2bfloat16(h0);
    hi[dst + d + 32] = __float2bfloat16(h1);
    lo[dst + d]      = __float2bfloat16(y0 - h0);
    lo[dst + d + 32] = __float2bfloat16(y1 - h1);
}

// ============================================================================
// V split + relayout: fp32 [B,S,NKV,HD] -> bf16 hi/lo [B,NKV,S,HD]
// ============================================================================
__global__ void splitv_kernel(const float* __restrict__ x,
                              __nv_bfloat16* __restrict__ hi,
                              __nv_bfloat16* __restrict__ lo)
{
    int i = blockIdx.x * blockDim.x + threadIdx.x;
    const int total4 = B_ * S_ * NKV_ * HD_ / 4;
    if (i >= total4) return;
    int d4 = i & 15; int r = i >> 4;
    int h = r & 7; r >>= 3;
    int s = r & (S_ - 1);
    int b = r >> 11;

    float4 v = *(const float4*)(x + ((((size_t)b * S_ + s) * NKV_ + h) * HD_) + d4 * 4);
    size_t dst = (((size_t)b * NKV_ + h) * S_ + s) * HD_ + d4 * 4;
    float h0 = __bfloat162float(__float2bfloat16(v.x));
    float h1 = __bfloat162float(__float2bfloat16(v.y));
    float h2 = __bfloat162float(__float2bfloat16(v.z));
    float h3 = __bfloat162float(__float2bfloat16(v.w));
    *(uint32_t*)(hi + dst)     = pkbf(h0, h1);
    *(uint32_t*)(hi + dst + 2) = pkbf(h2, h3);
    *(uint32_t*)(lo + dst)     = pkbf(v.x - h0, v.y - h1);
    *(uint32_t*)(lo + dst + 2) = pkbf(v.z - h2, v.w - h3);
}

// ============================================================================
// Flash attention v2 on HMMA (split-bf16 3-term for QK^T and PV).
// CTA = 128 q-rows of one head; 8 warps x 16 rows. 64-kv chunks, cp.async
// double buffer. P reused in registers (C-frag -> A-frag mapping).
// smem: KV stages @0/36864 (Kh,Kl,Vh,Vl 64x144B each), Qh @73728, Ql @92160.
// ============================================================================
#define LDR   144
#define KVT   9216
#define KVSTG 36864
#define QOFF  73728
#define ATTN_SMEM 110592

#define KVPREF(buf, kv0v) do { \
    int r_ = tid >> 2; int qc_ = (tid & 3) * 32; \
    uint32_t so_ = sb + (buf) * KVSTG + r_ * LDR + qc_; \
    const char* kh_ = (const char*)(Kh + kvb + (size_t)((kv0v) + r_) * HD_) + qc_; \
    const char* kl_ = (const char*)(Kl + kvb + (size_t)((kv0v) + r_) * HD_) + qc_; \
    const char* vh_ = (const char*)(Vh + kvb + (size_t)((kv0v) + r_) * HD_) + qc_; \
    const char* vl_ = (const char*)(Vl + kvb + (size_t)((kv0v) + r_) * HD_) + qc_; \
    cp16(so_, kh_);           cp16(so_ + 16, kh_ + 16); \
    cp16(so_ + KVT, kl_);     cp16(so_ + KVT + 16, kl_ + 16); \
    cp16(so_ + 2*KVT, vh_);   cp16(so_ + 2*KVT + 16, vh_ + 16); \
    cp16(so_ + 3*KVT, vl_);   cp16(so_ + 3*KVT + 16, vl_ + 16); \
    CP_COMMIT(); \
} while (0)

__global__ __launch_bounds__(256, 2) void attn_hmma_kernel(
    const __nv_bfloat16* __restrict__ Qh, const __nv_bfloat16* __restrict__ Ql,
    const __nv_bfloat16* __restrict__ Kh, const __nv_bfloat16* __restrict__ Kl,
    const __nv_bfloat16* __restrict__ Vh, const __nv_bfloat16* __restrict__ Vl)
{
    extern __shared__ char sm[];
    const uint32_t sb = smem_u32(sm);
    const int qt = (S_ / 128 - 1) - blockIdx.x;   // long tiles first
    const int h = blockIdx.y, b = blockIdx.z;
    const int hkv = h >> 2;
    const int tid = threadIdx.x, lane = tid & 31, w = tid >> 5;
    const int wq = w * 16, q0 = qt * 128;
    const int lmr = lane & 15, lmc = lane >> 4;
    const int g = lane >> 2, qd = lane & 3;
    const int vtr = lane & 7, vselk = (lane >> 3) & 1, vseln = lane >> 4;

    const __nv_bfloat16* qhp = Qh + ((size_t)(b * NH_ + h) * S_ + q0) * HD_;
    const __nv_bfloat16* qlp = Ql + ((size_t)(b * NH_ + h) * S_ + q0) * HD_;
    const size_t kvb = (size_t)(b * NKV_ + hkv) * S_ * HD_;

    // ---- Q tiles into smem (once) ----
    {
        int r = tid >> 1;
        int cb = (tid & 1) * 64;
        uint32_t so = sb + QOFF + r * LDR + cb;
        const char* gh = (const char*)(qhp + (size_t)r * HD_) + cb;
        const char* gl = (const char*)(qlp + (size_t)r * HD_) + cb;
        cp16(so, gh);      cp16(so + 16, gh + 16);
        cp16(so + 32, gh + 32); cp16(so + 48, gh + 48);
        cp16(so + 18432, gl);      cp16(so + 18432 + 16, gl + 16);
        cp16(so + 18432 + 32, gl + 32); cp16(so + 18432 + 48, gl + 48);
        CP_COMMIT();
    }

    float m0 = -1e30f, m1 = -1e30f, l0 = 0.f, l1 = 0.f;
    float o[8][4];
#pragma unroll
    for (int nb = 0; nb < 8; nb++)
#pragma unroll
        for (int e = 0; e < 4; e++) o[nb][e] = 0.f;

    const int nch = 2 * (qt + 1);
    KVPREF(0, 0);

    for (int j = 0; j < nch; j++) {
        CP_WAIT0();
        __syncthreads();
        if (j + 1 < nch) KVPREF((j + 1) & 1, (j + 1) * 64);

        const uint32_t sKh = sb + (j & 1) * KVSTG;
        const uint32_t sKl = sKh + KVT;
        const uint32_t sVh = sKh + 2 * KVT;
        const uint32_t sVl = sKh + 3 * KVT;

        // ---- S = Q K^T (3 terms) ----
        float sc[8][4];
#pragma unroll
        for (int nb = 0; nb < 8; nb++)
#pragma unroll
            for (int e = 0; e < 4; e++) sc[nb][e] = 0.f;

#pragma unroll
        for (int kt = 0; kt < 4; kt++) {
            uint32_t qh_[4], ql_[4];
            uint32_t qro = QOFF + (wq + lmr) * LDR + (kt * 2 + lmc) * 16;
            ldmx4(qh_, sb + qro);
            ldmx4(ql_, sb + qro + 18432);
#pragma unroll
            for (int ng = 0; ng < 4; ng++) {
                uint32_t kh_[4], kl_[4];
                uint32_t kro = (ng * 16 + lmr) * LDR + (kt * 2 + lmc) * 16;
                ldmx4(kh_, sKh + kro);
                ldmx4(kl_, sKl + kro);
                mma16816(sc[2 * ng],     qh_, kh_[0], kh_[2]);
                mma16816(sc[2 * ng + 1], qh_, kh_[1], kh_[3]);
                mma16816(sc[2 * ng],     ql_, kh_[0], kh_[2]);
                mma16816(sc[2 * ng + 1], ql_, kh_[1], kh_[3]);
                mma16816(sc[2 * ng],     qh_, kl_[0], kl_[2]);
                mma16816(sc[2 * ng + 1], qh_, kl_[1], kl_[3]);
            }
        }

        // ---- causal mask ----
        const int kv0 = j * 64;
        if (kv0 + 63 > q0 + wq) {
            int row0 = q0 + wq + g;
#pragma unroll
            for (int nb = 0; nb < 8; nb++) {
                int col = kv0 + nb * 8 + qd * 2;
                if (col > row0)         sc[nb][0] = -1e30f;
                if (col + 1 > row0)     sc[nb][1] = -1e30f;
                if (col > row0 + 8)     sc[nb][2] = -1e30f;
                if (col + 1 > row0 + 8) sc[nb][3] = -1e30f;
            }
        }

        // ---- online softmax ----
        float mx0 = -1e30f, mx1 = -1e30f;
#pragma unroll
        for (int nb = 0; nb < 8; nb++) {
            mx0 = fmaxf(mx0, fmaxf(sc[nb][0], sc[nb][1]));
            mx1 = fmaxf(mx1, fmaxf(sc[nb][2], sc[nb][3]));
        }
        mx0 = fmaxf(mx0, __shfl_xor_sync(0xffffffffu, mx0, 1));
        mx0 = fmaxf(mx0, __shfl_xor_sync(0xffffffffu, mx0, 2));
        mx1 = fmaxf(mx1, __shfl_xor_sync(0xffffffffu, mx1, 1));
        mx1 = fmaxf(mx1, __shfl_xor_sync(0xffffffffu, mx1, 2));
        float nm0 = fmaxf(m0, mx0), nm1 = fmaxf(m1, mx1);
        float a0 = __expf(m0 - nm0), a1 = __expf(m1 - nm1);
        float rs0 = 0.f, rs1 = 0.f;
#pragma unroll
        for (int nb = 0; nb < 8; nb++) {
            sc[nb][0] = __expf(sc[nb][0] - nm0);
            sc[nb][1] = __expf(sc[nb][1] - nm0);
            sc[nb][2] = __expf(sc[nb][2] - nm1);
            sc[nb][3] = __expf(sc[nb][3] - nm1);
            rs0 += sc[nb][0] + sc[nb][1];
            rs1 += sc[nb][2] + sc[nb][3];
        }
        rs0 += __shfl_xor_sync(0xffffffffu, rs0, 1);
        rs0 += __shfl_xor_sync(0xffffffffu, rs0, 2);
        rs1 += __shfl_xor_sync(0xffffffffu, rs1, 1);
        rs1 += __shfl_xor_sync(0xffffffffu, rs1, 2);
        l0 = l0 * a0 + rs0; l1 = l1 * a1 + rs1;
        m0 = nm0; m1 = nm1;
#pragma unroll
        for (int nb = 0; nb < 8; nb++) {
            o[nb][0] *= a0; o[nb][1] *= a0;
            o[nb][2] *= a1; o[nb][3] *= a1;
        }

        // ---- O += P V (3 terms), P from registers ----
#pragma unroll
        for (int kt = 0; kt < 4; kt++) {
            uint32_t pha[4], pla[4];
            splitpk(sc[2 * kt][0],     sc[2 * kt][1],     pha[0], pla[0]);
            splitpk(sc[2 * kt][2],     sc[2 * kt][3],     pha[1], pla[1]);
            splitpk(sc[2 * kt + 1][0], sc[2 * kt + 1][1], pha[2], pla[2]);
            splitpk(sc[2 * kt + 1][2], sc[2 * kt + 1][3], pha[3], pla[3]);
            uint32_t vrow = (kt * 16 + vselk * 8 + vtr) * LDR;
#pragma unroll
            for (int nb2 = 0; nb2 < 4; nb2++) {
                uint32_t vh_[4], vl_[4];
                uint32_t vro = vrow + (nb2 * 2 + vseln) * 16;
                ldmx4t(vh_, sVh + vro);
                ldmx4t(vl_, sVl + vro);
                mma16816(o[2 * nb2],     pha, vh_[0], vh_[1]);
                mma16816(o[2 * nb2],     pla, vh_[0], vh_[1]);
                mma16816(o[2 * nb2],     pha, vl_[0], vl_[1]);
                mma16816(o[2 * nb2 + 1], pha, vh_[2], vh_[3]);
                mma16816(o[2 * nb2 + 1], pla, vh_[2], vh_[3]);
                mma16816(o[2 * nb2 + 1], pha, vl_[2], vl_[3]);
            }
        }
    }

    // ---- epilogue ----
    float i0 = 1.f / l0, i1 = 1.f / l1;
    float* op  = g_o + ((size_t)b * S_ + q0 + wq + g) * (NH_ * HD_) + h * HD_;
    float* op8 = op + (size_t)8 * NH_ * HD_;
#pragma unroll
    for (int nb = 0; nb < 8; nb++) {
        int col = nb * 8 + qd * 2;
        *(float2*)(op + col)  = make_float2(o[nb][0] * i0, o[nb][1] * i0);
        *(float2*)(op8 + col) = make_float2(o[nb][2] * i1, o[nb][3] * i1);
    }
}

// ============================================================================
extern "C" void kernel_launch(void* const* d_in, const int* in_sizes, int n_in,
                              void* d_out, int out_size)
{
    const float* hs = (const float*)d_in[0];
    const float* Wq = (const float*)d_in[1];
    const float* Wk = (const float*)d_in[2];
    const float* Wv = (const float*)d_in[3];
    const float* Wo = (const float*)d_in[4];
    float* out = (float*)d_out;

    float *qp, *kp, *vp, *op;
    __nv_bfloat16 *hsh, *hsl, *wh, *wl, *ohh, *ohl;
    __nv_bfloat16 *qh, *ql, *kh, *kl, *vh, *vl;
    cudaGetSymbolAddress((void**)&qp, g_q);
    cudaGetSymbolAddress((void**)&kp, g_k);
    cudaGetSymbolAddress((void**)&vp, g_v);
    cudaGetSymbolAddress((void**)&op, g_o);
    cudaGetSymbolAddress((void**)&hsh, g_hs_hi);
    cudaGetSymbolAddress((void**)&hsl, g_hs_lo);
    cudaGetSymbolAddress((void**)&wh, g_w_hi);
    cudaGetSymbolAddress((void**)&wl, g_w_lo);
    cudaGetSymbolAddress((void**)&ohh, g_oh_hi);
    cudaGetSymbolAddress((void**)&ohl, g_oh_lo);
    cudaGetSymbolAddress((void**)&qh, g_qh);
    cudaGetSymbolAddress((void**)&ql, g_ql);
    cudaGetSymbolAddress((void**)&kh, g_kh2);
    cudaGetSymbolAddress((void**)&kl, g_kl2);
    cudaGetSymbolAddress((void**)&vh, g_vh2);
    cudaGetSymbolAddress((void**)&vl, g_vl2);

    const int M = B_ * S_;
    const int nHS = B_ * S_ * H_;
    const int nWqo = H_ * H_;
    const int nWkv = NKV_ * HD_ * H_;

    cudaFuncSetAttribute(gemm_bf16_kernel, cudaFuncAttributeMaxDynamicSharedMemorySize, GEMM_SMEM);
    cudaFuncSetAttribute(attn_hmma_kernel, cudaFuncAttributeMaxDynamicSharedMemorySize, ATTN_SMEM);

    // split hidden states
    split_kernel<<<nHS / 4 / 256, 256>>>(hs, hsh, hsl, nHS / 4);

    // QKV projections
    split_kernel<<<nWqo / 4 / 256, 256>>>(Wq, wh, wl, nWqo / 4);
    gemm_bf16_kernel<<<dim3(16, 32), 256, GEMM_SMEM>>>(hsh, hsl, wh, wl, qp, M, NH_ * HD_, H_);
    split_kernel<<<nWkv / 4 / 256, 256>>>(Wk, wh, wl, nWkv / 4);
    gemm_bf16_kernel<<<dim3(4, 32), 256, GEMM_SMEM>>>(hsh, hsl, wh, wl, kp, M, NKV_ * HD_, H_);
    split_kernel<<<nWkv / 4 / 256, 256>>>(Wv, wh, wl, nWkv / 4);
    gemm_bf16_kernel<<<dim3(4, 32), 256, GEMM_SMEM>>>(hsh, hsl, wh, wl, vp, M, NKV_ * HD_, H_);

    // RoPE + split + relayout (Q scaled by 1/8); V split
    rope_split_kernel<<<(B_ * S_ * NH_ * 32) / 256, 256>>>(qp, qh, ql, NH_, 0.125f);
    rope_split_kernel<<<(B_ * S_ * NKV_ * 32) / 256, 256>>>(kp, kh, kl, NKV_, 1.0f);
    splitv_kernel<<<(B_ * S_ * NKV_ * HD_ / 4) / 256, 256>>>(vp, vh, vl);

    // attention (HMMA)
    attn_hmma_kernel<<<dim3(S_ / 128, NH_, B_), 256, ATTN_SMEM>>>(qh, ql, kh, kl, vh, vl);

    // out-proj
    split_kernel<<<nHS / 4 / 256, 256>>>(op, ohh, ohl, nHS / 4);
    split_kernel<<<nWqo / 4 / 256, 256>>>(Wo, wh, wl, nWqo / 4);
    gemm_bf16_kernel<<<dim3(16, 32), 256, GEMM_SMEM>>>(ohh, ohl, wh, wl, out, M, H_, H_);
}

// round 12
// speedup vs baseline: 4.0701x; 1.4292x over previous
#include <cuda_runtime.h>
#include <cuda_fp16.h>
#include <math.h>
#include <cstdint>

// Problem dims
#define B_   2
#define S_   2048
#define H_   2048
#define NH_  32
#define NKV_ 8
#define HD_  64

// fp32 scratch
__device__ float g_q[(size_t)B_ * S_ * NH_ * HD_];
__device__ float g_k[(size_t)B_ * S_ * NKV_ * HD_];
__device__ float g_v[(size_t)B_ * S_ * NKV_ * HD_];
__device__ float g_o[(size_t)B_ * S_ * NH_ * HD_];

// fp16 scratch
__device__ __half g_hs_hi[(size_t)B_ * S_ * H_];
__device__ __half g_hs_lo[(size_t)B_ * S_ * H_];
__device__ __half g_w_hi[(size_t)H_ * H_];
__device__ __half g_oh_hi[(size_t)B_ * S_ * NH_ * HD_];
__device__ __half g_oh_lo[(size_t)B_ * S_ * NH_ * HD_];
// attention operands, head-major [B, heads, S, HD]
__device__ __half g_qh[(size_t)B_ * NH_ * S_ * HD_];
__device__ __half g_ql[(size_t)B_ * NH_ * S_ * HD_];
__device__ __half g_kh2[(size_t)B_ * NKV_ * S_ * HD_];
__device__ __half g_vh2[(size_t)B_ * NKV_ * S_ * HD_];

// ---- mma.sync / ldmatrix / cp.async helpers ----
__device__ __forceinline__ uint32_t smem_u32(const void* p) {
    uint32_t a;
    asm("{ .reg .u64 t; cvta.to.shared.u64 t, %1; cvt.u32.u64 %0, t; }" : "=r"(a) : "l"(p));
    return a;
}
__device__ __forceinline__ void ldmx4(uint32_t* r, uint32_t addr) {
    asm volatile("ldmatrix.sync.aligned.m8n8.x4.shared.b16 {%0,%1,%2,%3}, [%4];"
                 : "=r"(r[0]), "=r"(r[1]), "=r"(r[2]), "=r"(r[3]) : "r"(addr));
}
__device__ __forceinline__ void ldmx4t(uint32_t* r, uint32_t addr) {
    asm volatile("ldmatrix.sync.aligned.m8n8.x4.trans.shared.b16 {%0,%1,%2,%3}, [%4];"
                 : "=r"(r[0]), "=r"(r[1]), "=r"(r[2]), "=r"(r[3]) : "r"(addr));
}
__device__ __forceinline__ void mma16816(float* c, const uint32_t* a, uint32_t b0, uint32_t b1) {
    asm volatile("mma.sync.aligned.m16n8k16.row.col.f32.f16.f16.f32 "
                 "{%0,%1,%2,%3}, {%4,%5,%6,%7}, {%8,%9}, {%0,%1,%2,%3};"
                 : "+f"(c[0]), "+f"(c[1]), "+f"(c[2]), "+f"(c[3])
                 : "r"(a[0]), "r"(a[1]), "r"(a[2]), "r"(a[3]), "r"(b0), "r"(b1));
}
__device__ __forceinline__ void cp16(uint32_t s, const void* g) {
    asm volatile("cp.async.ca.shared.global [%0], [%1], 16;" :: "r"(s), "l"(g));
}
#define CP_COMMIT() asm volatile("cp.async.commit_group;" ::: "memory")
#define CP_WAIT0()  asm volatile("cp.async.wait_group 0;" ::: "memory")

__device__ __forceinline__ uint32_t pkhf(float x, float y) {
    __half2 t = __floats2half2_rn(x, y);
    return *(uint32_t*)&t;
}
__device__ __forceinline__ void splitpk(float x, float y, uint32_t& hi, uint32_t& lo) {
    float hx = __half2float(__float2half_rn(x));
    float hy = __half2float(__float2half_rn(y));
    hi = pkhf(hx, hy);
    lo = pkhf(x - hx, y - hy);
}

// ============================================================================
// split: fp32 -> fp16 hi + lo
// ============================================================================
__global__ void split_kernel(const float* __restrict__ x,
                             __half* __restrict__ hi,
                             __half* __restrict__ lo, int n4)
{
    int i = blockIdx.x * blockDim.x + threadIdx.x;
    if (i >= n4) return;
    float4 v = *(const float4*)(x + (size_t)i * 4);
    float h0 = __half2float(__float2half_rn(v.x));
    float h1 = __half2float(__float2half_rn(v.y));
    float h2 = __half2float(__float2half_rn(v.z));
    float h3 = __half2float(__float2half_rn(v.w));
    *(uint32_t*)(hi + (size_t)i * 4)     = pkhf(h0, h1);
    *(uint32_t*)(hi + (size_t)i * 4 + 2) = pkhf(h2, h3);
    *(uint32_t*)(lo + (size_t)i * 4)     = pkhf(v.x - h0, v.y - h1);
    *(uint32_t*)(lo + (size_t)i * 4 + 2) = pkhf(v.z - h2, v.w - h3);
}

// round: fp32 -> fp16 (weights)
__global__ void round_kernel(const float* __restrict__ x,
                             __half* __restrict__ hi, int n4)
{
    int i = blockIdx.x * blockDim.x + threadIdx.x;
    if (i >= n4) return;
    float4 v = *(const float4*)(x + (size_t)i * 4);
    *(uint32_t*)(hi + (size_t)i * 4)     = pkhf(v.x, v.y);
    *(uint32_t*)(hi + (size_t)i * 4 + 2) = pkhf(v.z, v.w);
}

// ============================================================================
// HMMA GEMM: C[M,N] = A[M,K] * W[N,K]^T, 2-term fp16 (A split, W rounded):
// C ~= (Ah+Al) * Wh.  128x128 tile, BK=32, 8 warps (2x4, 64x32 warp tiles).
// cp.async double buffer; rows padded to 80B (conflict-free ldmatrix).
// ============================================================================
#define LDB   80
#define TILEB (128 * LDB)
#define STAGEB (3 * TILEB)       // Ah, Al, Bh
#define GEMM_SMEM (2 * STAGEB)   // 61440

#define PREFETCH(buf, kcv) do { \
    size_t goff = (size_t)(kcv) * 32 + lc2 * 8; \
    uint32_t sro = (buf) * STAGEB + lrow * LDB + lc2 * 16; \
    const __half* _ga = Ahi + (size_t)(bm + lrow) * K + goff; \
    const __half* _gl = Alo + (size_t)(bm + lrow) * K + goff; \
    const __half* _gb = Bh  + (size_t)(bn + lrow) * K + goff; \
    cp16(sbase + sro,             _ga); cp16(sbase + sro + 16,             _ga + 8); \
    cp16(sbase + sro + TILEB,     _gl); cp16(sbase + sro + TILEB + 16,     _gl + 8); \
    cp16(sbase + sro + 2 * TILEB, _gb); cp16(sbase + sro + 2 * TILEB + 16, _gb + 8); \
    CP_COMMIT(); \
} while (0)

__global__ __launch_bounds__(256, 2) void gemm_fp16_kernel(
    const __half* __restrict__ Ahi, const __half* __restrict__ Alo,
    const __half* __restrict__ Bh,
    float* __restrict__ C, int M, int N, int K)
{
    extern __shared__ char smemg[];
    const uint32_t sbase = smem_u32(smemg);
    const int tid = threadIdx.x;
    const int lane = tid & 31, w = tid >> 5;
    const int wm = (w >> 2) * 64, wn = (w & 3) * 32;
    const int bm = blockIdx.y * 128, bn = blockIdx.x * 128;
    const int lrow = tid >> 1, lc2 = (tid & 1) * 2;
    const int lmr = lane & 15, lmc = lane >> 4;

    float acc[4][4][4];
#pragma unroll
    for (int a = 0; a < 4; a++)
#pragma unroll
        for (int b = 0; b < 4; b++)
#pragma unroll
            for (int c = 0; c < 4; c++) acc[a][b][c] = 0.f;

    const int nch = K >> 5;
    PREFETCH(0, 0);

    for (int it = 0; it < nch; it++) {
        CP_WAIT0();
        __syncthreads();
        if (it + 1 < nch) PREFETCH((it + 1) & 1, it + 1);

        const uint32_t sAh = sbase + (it & 1) * STAGEB;
        const uint32_t sAl = sAh + TILEB;
        const uint32_t sBh = sAh + 2 * TILEB;
#pragma unroll
        for (int kk = 0; kk < 2; kk++) {
            uint32_t bh[2][4];
#pragma unroll
            for (int nh = 0; nh < 2; nh++)
                ldmx4(bh[nh], sBh + (wn + nh * 16 + lmr) * LDB + (kk * 2 + lmc) * 16);
#pragma unroll
            for (int mi = 0; mi < 4; mi++) {
                uint32_t ah[4], al[4];
                uint32_t ro = (wm + mi * 16 + lmr) * LDB + (kk * 2 + lmc) * 16;
                ldmx4(ah, sAh + ro);
                ldmx4(al, sAl + ro);
#pragma unroll
                for (int nh = 0; nh < 2; nh++) {
                    mma16816(acc[mi][nh * 2 + 0], ah, bh[nh][0], bh[nh][2]);
                    mma16816(acc[mi][nh * 2 + 1], ah, bh[nh][1], bh[nh][3]);
                    mma16816(acc[mi][nh * 2 + 0], al, bh[nh][0], bh[nh][2]);
                    mma16816(acc[mi][nh * 2 + 1], al, bh[nh][1], bh[nh][3]);
                }
            }
        }
        __syncthreads();
    }

    const int er = lane >> 2, ec = (lane & 3) * 2;
#pragma unroll
    for (int mi = 0; mi < 4; mi++)
#pragma unroll
        for (int ni = 0; ni < 4; ni++) {
            size_t row = (size_t)(bm + wm + mi * 16 + er);
            size_t col = (size_t)(bn + wn + ni * 8 + ec);
            *(float2*)&C[row * N + col]       = make_float2(acc[mi][ni][0], acc[mi][ni][1]);
            *(float2*)&C[(row + 8) * N + col] = make_float2(acc[mi][ni][2], acc[mi][ni][3]);
        }
}

// ============================================================================
// RoPE + split + relayout (Q): fp32 [B,S,nh,HD] -> fp16 hi/lo [B,nh,S,HD].
// ============================================================================
__global__ void rope_split_kernel(const float* __restrict__ x,
                                  __half* __restrict__ hi,
                                  __half* __restrict__ lo, int nheads)
{
    int idx = blockIdx.x * blockDim.x + threadIdx.x;
    int total = B_ * S_ * nheads * 32;
    if (idx >= total) return;
    int d = idx & 31;
    int r = idx >> 5;
    int h = r % nheads; r /= nheads;
    int s = r % S_;
    int b = r / S_;

    float inv = exp2f((float)d * -0.41524101186f);
    float fr = (float)s * inv;
    float c, sn;
    sincosf(fr, &sn, &c);

    size_t src = (((size_t)b * S_ + s) * nheads + h) * HD_;
    float x0 = x[src + d], x1 = x[src + d + 32];
    float y0 = x0 * c - x1 * sn;
    float y1 = x1 * c + x0 * sn;

    size_t dst = (((size_t)b * nheads + h) * S_ + s) * HD_;
    float h0 = __half2float(__float2half_rn(y0));
    float h1 = __half2float(__float2half_rn(y1));
    hi[dst + d]      = __float2half_rn(h0);
    hi[dst + d + 32] = __float2half_rn(h1);
    lo[dst + d]      = __float2half_rn(y0 - h0);
    lo[dst + d + 32] = __float2half_rn(y1 - h1);
}

// RoPE + round + relayout (K): scale folded here (1/8).
__global__ void rope_round_kernel(const float* __restrict__ x,
                                  __half* __restrict__ hi, int nheads, float scale)
{
    int idx = blockIdx.x * blockDim.x + threadIdx.x;
    int total = B_ * S_ * nheads * 32;
    if (idx >= total) return;
    int d = idx & 31;
    int r = idx >> 5;
    int h = r % nheads; r /= nheads;
    int s = r % S_;
    int b = r / S_;

    float inv = exp2f((float)d * -0.41524101186f);
    float fr = (float)s * inv;
    float c, sn;
    sincosf(fr, &sn, &c);

    size_t src = (((size_t)b * S_ + s) * nheads + h) * HD_;
    float x0 = x[src + d], x1 = x[src + d + 32];
    size_t dst = (((size_t)b * nheads + h) * S_ + s) * HD_;
    hi[dst + d]      = __float2half_rn((x0 * c - x1 * sn) * scale);
    hi[dst + d + 32] = __float2half_rn((x1 * c + x0 * sn) * scale);
}

// V round + relayout: fp32 [B,S,NKV,HD] -> fp16 [B,NKV,S,HD]
__global__ void roundv_kernel(const float* __restrict__ x,
                              __half* __restrict__ hi)
{
    int i = blockIdx.x * blockDim.x + threadIdx.x;
    const int total4 = B_ * S_ * NKV_ * HD_ / 4;
    if (i >= total4) return;
    int d4 = i & 15; int r = i >> 4;
    int h = r & 7; r >>= 3;
    int s = r & (S_ - 1);
    int b = r >> 11;

    float4 v = *(const float4*)(x + ((((size_t)b * S_ + s) * NKV_ + h) * HD_) + d4 * 4);
    size_t dst = (((size_t)b * NKV_ + h) * S_ + s) * HD_ + d4 * 4;
    *(uint32_t*)(hi + dst)     = pkhf(v.x, v.y);
    *(uint32_t*)(hi + dst + 2) = pkhf(v.z, v.w);
}

// ============================================================================
// Flash attention v2 on HMMA, 2-term fp16: S = (Qh+Ql)*Kh, O = (Ph+Pl)*Vh.
// CTA = 128 q-rows; 8 warps x 16 rows; 64-kv double-buffered chunks.
// smem: [Kh,Vh] stages @0/18432; Qh @36864, Ql @55296. 73728 B total.
// ============================================================================
#define LDR   144
#define KVT   9216
#define KVSTG 18432
#define QOFF  36864
#define ATTN_SMEM 73728

#define KVPREF(buf, kv0v) do { \
    int r_ = tid >> 2; int qc_ = (tid & 3) * 32; \
    uint32_t so_ = sb + (buf) * KVSTG + r_ * LDR + qc_; \
    const char* kh_ = (const char*)(Kh + kvb + (size_t)((kv0v) + r_) * HD_) + qc_; \
    const char* vh_ = (const char*)(Vh + kvb + (size_t)((kv0v) + r_) * HD_) + qc_; \
    cp16(so_, kh_);         cp16(so_ + 16, kh_ + 16); \
    cp16(so_ + KVT, vh_);   cp16(so_ + KVT + 16, vh_ + 16); \
    CP_COMMIT(); \
} while (0)

__global__ __launch_bounds__(256, 2) void attn_hmma_kernel(
    const __half* __restrict__ Qh, const __half* __restrict__ Ql,
    const __half* __restrict__ Kh, const __half* __restrict__ Vh)
{
    extern __shared__ char sm[];
    const uint32_t sb = smem_u32(sm);
    const int qt = (S_ / 128 - 1) - blockIdx.x;
    const int h = blockIdx.y, b = blockIdx.z;
    const int hkv = h >> 2;
    const int tid = threadIdx.x, lane = tid & 31, w = tid >> 5;
    const int wq = w * 16, q0 = qt * 128;
    const int lmr = lane & 15, lmc = lane >> 4;
    const int g = lane >> 2, qd = lane & 3;
    const int vtr = lane & 7, vselk = (lane >> 3) & 1, vseln = lane >> 4;

    const __half* qhp = Qh + ((size_t)(b * NH_ + h) * S_ + q0) * HD_;
    const __half* qlp = Ql + ((size_t)(b * NH_ + h) * S_ + q0) * HD_;
    const size_t kvb = (size_t)(b * NKV_ + hkv) * S_ * HD_;

    // Q tiles into smem (once)
    {
        int r = tid >> 1;
        int cb = (tid & 1) * 64;
        uint32_t so = sb + QOFF + r * LDR + cb;
        const char* gh = (const char*)(qhp + (size_t)r * HD_) + cb;
        const char* gl = (const char*)(qlp + (size_t)r * HD_) + cb;
        cp16(so, gh);      cp16(so + 16, gh + 16);
        cp16(so + 32, gh + 32); cp16(so + 48, gh + 48);
        cp16(so + 18432, gl);      cp16(so + 18432 + 16, gl + 16);
        cp16(so + 18432 + 32, gl + 32); cp16(so + 18432 + 48, gl + 48);
        CP_COMMIT();
    }

    float m0 = -1e30f, m1 = -1e30f, l0 = 0.f, l1 = 0.f;
    float o[8][4];
#pragma unroll
    for (int nb = 0; nb < 8; nb++)
#pragma unroll
        for (int e = 0; e < 4; e++) o[nb][e] = 0.f;

    const int nch = 2 * (qt + 1);
    KVPREF(0, 0);

    for (int j = 0; j < nch; j++) {
        CP_WAIT0();
        __syncthreads();
        if (j + 1 < nch) KVPREF((j + 1) & 1, (j + 1) * 64);

        const uint32_t sKh = sb + (j & 1) * KVSTG;
        const uint32_t sVh = sKh + KVT;

        // ---- S = Q Kh^T (2 terms) ----
        float sc[8][4];
#pragma unroll
        for (int nb = 0; nb < 8; nb++)
#pragma unroll
            for (int e = 0; e < 4; e++) sc[nb][e] = 0.f;

#pragma unroll
        for (int kt = 0; kt < 4; kt++) {
            uint32_t qh_[4], ql_[4];
            uint32_t qro = QOFF + (wq + lmr) * LDR + (kt * 2 + lmc) * 16;
            ldmx4(qh_, sb + qro);
            ldmx4(ql_, sb + qro + 18432);
#pragma unroll
            for (int ng = 0; ng < 4; ng++) {
                uint32_t kh_[4];
                ldmx4(kh_, sKh + (ng * 16 + lmr) * LDR + (kt * 2 + lmc) * 16);
                mma16816(sc[2 * ng],     qh_, kh_[0], kh_[2]);
                mma16816(sc[2 * ng + 1], qh_, kh_[1], kh_[3]);
                mma16816(sc[2 * ng],     ql_, kh_[0], kh_[2]);
                mma16816(sc[2 * ng + 1], ql_, kh_[1], kh_[3]);
            }
        }

        // ---- causal mask ----
        const int kv0 = j * 64;
        if (kv0 + 63 > q0 + wq) {
            int row0 = q0 + wq + g;
#pragma unroll
            for (int nb = 0; nb < 8; nb++) {
                int col = kv0 + nb * 8 + qd * 2;
                if (col > row0)         sc[nb][0] = -1e30f;
                if (col + 1 > row0)     sc[nb][1] = -1e30f;
                if (col > row0 + 8)     sc[nb][2] = -1e30f;
                if (col + 1 > row0 + 8) sc[nb][3] = -1e30f;
            }
        }

        // ---- online softmax ----
        float mx0 = -1e30f, mx1 = -1e30f;
#pragma unroll
        for (int nb = 0; nb < 8; nb++) {
            mx0 = fmaxf(mx0, fmaxf(sc[nb][0], sc[nb][1]));
            mx1 = fmaxf(mx1, fmaxf(sc[nb][2], sc[nb][3]));
        }
        mx0 = fmaxf(mx0, __shfl_xor_sync(0xffffffffu, mx0, 1));
        mx0 = fmaxf(mx0, __shfl_xor_sync(0xffffffffu, mx0, 2));
        mx1 = fmaxf(mx1, __shfl_xor_sync(0xffffffffu, mx1, 1));
        mx1 = fmaxf(mx1, __shfl_xor_sync(0xffffffffu, mx1, 2));
        float nm0 = fmaxf(m0, mx0), nm1 = fmaxf(m1, mx1);
        float a0 = __expf(m0 - nm0), a1 = __expf(m1 - nm1);
        float rs0 = 0.f, rs1 = 0.f;
#pragma unroll
        for (int nb = 0; nb < 8; nb++) {
            sc[nb][0] = __expf(sc[nb][0] - nm0);
            sc[nb][1] = __expf(sc[nb][1] - nm0);
            sc[nb][2] = __expf(sc[nb][2] - nm1);
            sc[nb][3] = __expf(sc[nb][3] - nm1);
            rs0 += sc[nb][0] + sc[nb][1];
            rs1 += sc[nb][2] + sc[nb][3];
        }
        rs0 += __shfl_xor_sync(0xffffffffu, rs0, 1);
        rs0 += __shfl_xor_sync(0xffffffffu, rs0, 2);
        rs1 += __shfl_xor_sync(0xffffffffu, rs1, 1);
        rs1 += __shfl_xor_sync(0xffffffffu, rs1, 2);
        l0 = l0 * a0 + rs0; l1 = l1 * a1 + rs1;
        m0 = nm0; m1 = nm1;
#pragma unroll
        for (int nb = 0; nb < 8; nb++) {
            o[nb][0] *= a0; o[nb][1] *= a0;
            o[nb][2] *= a1; o[nb][3] *= a1;
        }

        // ---- O += P Vh (2 terms), P split from registers ----
#pragma unroll
        for (int kt = 0; kt < 4; kt++) {
            uint32_t pha[4], pla[4];
            splitpk(sc[2 * kt][0],     sc[2 * kt][1],     pha[0], pla[0]);
            splitpk(sc[2 * kt][2],     sc[2 * kt][3],     pha[1], pla[1]);
            splitpk(sc[2 * kt + 1][0], sc[2 * kt + 1][1], pha[2], pla[2]);
            splitpk(sc[2 * kt + 1][2], sc[2 * kt + 1][3], pha[3], pla[3]);
            uint32_t vrow = (kt * 16 + vselk * 8 + vtr) * LDR;
#pragma unroll
            for (int nb2 = 0; nb2 < 4; nb2++) {
                uint32_t vh_[4];
                ldmx4t(vh_, sVh + vrow + (nb2 * 2 + vseln) * 16);
                mma16816(o[2 * nb2],     pha, vh_[0], vh_[1]);
                mma16816(o[2 * nb2],     pla, vh_[0], vh_[1]);
                mma16816(o[2 * nb2 + 1], pha, vh_[2], vh_[3]);
                mma16816(o[2 * nb2 + 1], pla, vh_[2], vh_[3]);
            }
        }
    }

    // ---- epilogue ----
    float i0 = 1.f / l0, i1 = 1.f / l1;
    float* op  = g_o + ((size_t)b * S_ + q0 + wq + g) * (NH_ * HD_) + h * HD_;
    float* op8 = op + (size_t)8 * NH_ * HD_;
#pragma unroll
    for (int nb = 0; nb < 8; nb++) {
        int col = nb * 8 + qd * 2;
        *(float2*)(op + col)  = make_float2(o[nb][0] * i0, o[nb][1] * i0);
        *(float2*)(op8 + col) = make_float2(o[nb][2] * i1, o[nb][3] * i1);
    }
}

// ============================================================================
extern "C" void kernel_launch(void* const* d_in, const int* in_sizes, int n_in,
                              void* d_out, int out_size)
{
    const float* hs = (const float*)d_in[0];
    const float* Wq = (const float*)d_in[1];
    const float* Wk = (const float*)d_in[2];
    const float* Wv = (const float*)d_in[3];
    const float* Wo = (const float*)d_in[4];
    float* out = (float*)d_out;

    float *qp, *kp, *vp, *op;
    __half *hsh, *hsl, *wh, *ohh, *ohl, *qh, *ql, *kh, *vh;
    cudaGetSymbolAddress((void**)&qp, g_q);
    cudaGetSymbolAddress((void**)&kp, g_k);
    cudaGetSymbolAddress((void**)&vp, g_v);
    cudaGetSymbolAddress((void**)&op, g_o);
    cudaGetSymbolAddress((void**)&hsh, g_hs_hi);
    cudaGetSymbolAddress((void**)&hsl, g_hs_lo);
    cudaGetSymbolAddress((void**)&wh, g_w_hi);
    cudaGetSymbolAddress((void**)&ohh, g_oh_hi);
    cudaGetSymbolAddress((void**)&ohl, g_oh_lo);
    cudaGetSymbolAddress((void**)&qh, g_qh);
    cudaGetSymbolAddress((void**)&ql, g_ql);
    cudaGetSymbolAddress((void**)&kh, g_kh2);
    cudaGetSymbolAddress((void**)&vh, g_vh2);

    const int M = B_ * S_;
    const int nHS = B_ * S_ * H_;
    const int nWqo = H_ * H_;
    const int nWkv = NKV_ * HD_ * H_;

    cudaFuncSetAttribute(gemm_fp16_kernel, cudaFuncAttributeMaxDynamicSharedMemorySize, GEMM_SMEM);
    cudaFuncSetAttribute(attn_hmma_kernel, cudaFuncAttributeMaxDynamicSharedMemorySize, ATTN_SMEM);

    // split hidden states (activation side)
    split_kernel<<<nHS / 4 / 256, 256>>>(hs, hsh, hsl, nHS / 4);

    // QKV projections (weights rounded to fp16)
    round_kernel<<<nWqo / 4 / 256, 256>>>(Wq, wh, nWqo / 4);
    gemm_fp16_kernel<<<dim3(16, 32), 256, GEMM_SMEM>>>(hsh, hsl, wh, qp, M, NH_ * HD_, H_);
    round_kernel<<<nWkv / 4 / 256, 256>>>(Wk, wh, nWkv / 4);
    gemm_fp16_kernel<<<dim3(4, 32), 256, GEMM_SMEM>>>(hsh, hsl, wh, kp, M, NKV_ * HD_, H_);
    round_kernel<<<nWkv / 4 / 256, 256>>>(Wv, wh, nWkv / 4);
    gemm_fp16_kernel<<<dim3(4, 32), 256, GEMM_SMEM>>>(hsh, hsl, wh, vp, M, NKV_ * HD_, H_);

    // RoPE: Q split (unscaled); K rounded with 1/8 scale folded; V rounded
    rope_split_kernel<<<(B_ * S_ * NH_ * 32) / 256, 256>>>(qp, qh, ql, NH_);
    rope_round_kernel<<<(B_ * S_ * NKV_ * 32) / 256, 256>>>(kp, kh, NKV_, 0.125f);
    roundv_kernel<<<(B_ * S_ * NKV_ * HD_ / 4) / 256, 256>>>(vp, vh);

    // attention (HMMA, 2-term fp16)
    attn_hmma_kernel<<<dim3(S_ / 128, NH_, B_), 256, ATTN_SMEM>>>(qh, ql, kh, vh);

    // out-proj
    split_kernel<<<nHS / 4 / 256, 256>>>(op, ohh, ohl, nHS / 4);
    round_kernel<<<nWqo / 4 / 256, 256>>>(Wo, wh, nWqo / 4);
    gemm_fp16_kernel<<<dim3(16, 32), 256, GEMM_SMEM>>>(ohh, ohl, wh, out, M, H_, H_);
}

// round 13
// speedup vs baseline: 4.2306x; 1.0394x over previous
#include <cuda_runtime.h>
#include <cuda_fp16.h>
#include <math.h>
#include <cstdint>

// Problem dims
#define B_   2
#define S_   2048
#define H_   2048
#define NH_  32
#define NKV_ 8
#define HD_  64

// fp32 scratch (pre-rope Q/K/V)
__device__ float g_q[(size_t)B_ * S_ * NH_ * HD_];
__device__ float g_k[(size_t)B_ * S_ * NKV_ * HD_];
__device__ float g_v[(size_t)B_ * S_ * NKV_ * HD_];

// fp16 scratch
__device__ __half g_hs_hi[(size_t)B_ * S_ * H_];
__device__ __half g_hs_lo[(size_t)B_ * S_ * H_];
__device__ __half g_wq_hi[(size_t)H_ * H_];
__device__ __half g_wk_hi[(size_t)NKV_ * HD_ * H_];
__device__ __half g_wv_hi[(size_t)NKV_ * HD_ * H_];
__device__ __half g_wo_hi[(size_t)H_ * H_];
__device__ __half g_oh_hi[(size_t)B_ * S_ * NH_ * HD_];
__device__ __half g_oh_lo[(size_t)B_ * S_ * NH_ * HD_];
// attention operands, head-major [B, heads, S, HD]
__device__ __half g_qh[(size_t)B_ * NH_ * S_ * HD_];
__device__ __half g_ql[(size_t)B_ * NH_ * S_ * HD_];
__device__ __half g_kh2[(size_t)B_ * NKV_ * S_ * HD_];
__device__ __half g_vh2[(size_t)B_ * NKV_ * S_ * HD_];

// ---- mma.sync / ldmatrix / cp.async helpers ----
__device__ __forceinline__ uint32_t smem_u32(const void* p) {
    uint32_t a;
    asm("{ .reg .u64 t; cvta.to.shared.u64 t, %1; cvt.u32.u64 %0, t; }" : "=r"(a) : "l"(p));
    return a;
}
__device__ __forceinline__ void ldmx4(uint32_t* r, uint32_t addr) {
    asm volatile("ldmatrix.sync.aligned.m8n8.x4.shared.b16 {%0,%1,%2,%3}, [%4];"
                 : "=r"(r[0]), "=r"(r[1]), "=r"(r[2]), "=r"(r[3]) : "r"(addr));
}
__device__ __forceinline__ void ldmx4t(uint32_t* r, uint32_t addr) {
    asm volatile("ldmatrix.sync.aligned.m8n8.x4.trans.shared.b16 {%0,%1,%2,%3}, [%4];"
                 : "=r"(r[0]), "=r"(r[1]), "=r"(r[2]), "=r"(r[3]) : "r"(addr));
}
__device__ __forceinline__ void mma16816(float* c, const uint32_t* a, uint32_t b0, uint32_t b1) {
    asm volatile("mma.sync.aligned.m16n8k16.row.col.f32.f16.f16.f32 "
                 "{%0,%1,%2,%3}, {%4,%5,%6,%7}, {%8,%9}, {%0,%1,%2,%3};"
                 : "+f"(c[0]), "+f"(c[1]), "+f"(c[2]), "+f"(c[3])
                 : "r"(a[0]), "r"(a[1]), "r"(a[2]), "r"(a[3]), "r"(b0), "r"(b1));
}
__device__ __forceinline__ void cp16(uint32_t s, const void* g) {
    asm volatile("cp.async.ca.shared.global [%0], [%1], 16;" :: "r"(s), "l"(g));
}
#define CP_COMMIT() asm volatile("cp.async.commit_group;" ::: "memory")
#define CP_WAIT0()  asm volatile("cp.async.wait_group 0;" ::: "memory")

__device__ __forceinline__ uint32_t pkhf(float x, float y) {
    __half2 t = __floats2half2_rn(x, y);
    return *(uint32_t*)&t;
}
__device__ __forceinline__ void splitpk(float x, float y, uint32_t& hi, uint32_t& lo) {
    float hx = __half2float(__float2half_rn(x));
    float hy = __half2float(__float2half_rn(y));
    hi = pkhf(hx, hy);
    lo = pkhf(x - hx, y - hy);
}

// ============================================================================
// split: fp32 -> fp16 hi + lo
// ============================================================================
__global__ void split_kernel(const float* __restrict__ x,
                             __half* __restrict__ hi,
                             __half* __restrict__ lo, int n4)
{
    int i = blockIdx.x * blockDim.x + threadIdx.x;
    if (i >= n4) return;
    float4 v = *(const float4*)(x + (size_t)i * 4);
    float h0 = __half2float(__float2half_rn(v.x));
    float h1 = __half2float(__float2half_rn(v.y));
    float h2 = __half2float(__float2half_rn(v.z));
    float h3 = __half2float(__float2half_rn(v.w));
    *(uint32_t*)(hi + (size_t)i * 4)     = pkhf(h0, h1);
    *(uint32_t*)(hi + (size_t)i * 4 + 2) = pkhf(h2, h3);
    *(uint32_t*)(lo + (size_t)i * 4)     = pkhf(v.x - h0, v.y - h1);
    *(uint32_t*)(lo + (size_t)i * 4 + 2) = pkhf(v.z - h2, v.w - h3);
}

// round all four weight matrices in one launch
#define N4_WQ 1048576
#define N4_WK 262144
#define N4_WV 262144
#define N4_WO 1048576
__global__ void round4_kernel(const float* __restrict__ wq, const float* __restrict__ wk,
                              const float* __restrict__ wv, const float* __restrict__ wo,
                              __half* __restrict__ oq, __half* __restrict__ ok,
                              __half* __restrict__ ov, __half* __restrict__ oo)
{
    int i = blockIdx.x * blockDim.x + threadIdx.x;
    const float* src; __half* dst; int j;
    if (i < N4_WQ)                         { src = wq; dst = oq; j = i; }
    else if (i < N4_WQ + N4_WK)            { src = wk; dst = ok; j = i - N4_WQ; }
    else if (i < N4_WQ + N4_WK + N4_WV)    { src = wv; dst = ov; j = i - N4_WQ - N4_WK; }
    else if (i < N4_WQ + N4_WK + N4_WV + N4_WO)
                                           { src = wo; dst = oo; j = i - N4_WQ - N4_WK - N4_WV; }
    else return;
    float4 v = *(const float4*)(src + (size_t)j * 4);
    *(uint32_t*)(dst + (size_t)j * 4)     = pkhf(v.x, v.y);
    *(uint32_t*)(dst + (size_t)j * 4 + 2) = pkhf(v.z, v.w);
}

// ============================================================================
// HMMA GEMM body: C[*,N] tile (bm,bn) += A[M,K] * W[N,K]^T, 2-term fp16.
// 128x128 tile, BK=32, 8 warps (2x4, 64x32 warp tiles), cp.async dbl buffer.
// ============================================================================
#define LDB   80
#define TILEB (128 * LDB)
#define STAGEB (3 * TILEB)       // Ah, Al, Bh
#define GEMM_SMEM (2 * STAGEB)   // 61440

#define PREFETCH(buf, kcv) do { \
    size_t goff = (size_t)(kcv) * 32 + lc2 * 8; \
    uint32_t sro = (buf) * STAGEB + lrow * LDB + lc2 * 16; \
    const __half* _ga = Ahi + (size_t)(bm + lrow) * K + goff; \
    const __half* _gl = Alo + (size_t)(bm + lrow) * K + goff; \
    const __half* _gb = Bh  + (size_t)(bn + lrow) * K + goff; \
    cp16(sbase + sro,             _ga); cp16(sbase + sro + 16,             _ga + 8); \
    cp16(sbase + sro + TILEB,     _gl); cp16(sbase + sro + TILEB + 16,     _gl + 8); \
    cp16(sbase + sro + 2 * TILEB, _gb); cp16(sbase + sro + 2 * TILEB + 16, _gb + 8); \
    CP_COMMIT(); \
} while (0)

__device__ __forceinline__ void gemm_body(
    const __half* __restrict__ Ahi, const __half* __restrict__ Alo,
    const __half* __restrict__ Bh, float* __restrict__ C,
    int N, int K, int bm, int bn, uint32_t sbase)
{
    const int tid = threadIdx.x;
    const int lane = tid & 31, w = tid >> 5;
    const int wm = (w >> 2) * 64, wn = (w & 3) * 32;
    const int lrow = tid >> 1, lc2 = (tid & 1) * 2;
    const int lmr = lane & 15, lmc = lane >> 4;

    float acc[4][4][4];
#pragma unroll
    for (int a = 0; a < 4; a++)
#pragma unroll
        for (int b = 0; b < 4; b++)
#pragma unroll
            for (int c = 0; c < 4; c++) acc[a][b][c] = 0.f;

    const int nch = K >> 5;
    PREFETCH(0, 0);

    for (int it = 0; it < nch; it++) {
        CP_WAIT0();
        __syncthreads();
        if (it + 1 < nch) PREFETCH((it + 1) & 1, it + 1);

        const uint32_t sAh = sbase + (it & 1) * STAGEB;
        const uint32_t sAl = sAh + TILEB;
        const uint32_t sBh = sAh + 2 * TILEB;
#pragma unroll
        for (int kk = 0; kk < 2; kk++) {
            uint32_t bh[2][4];
#pragma unroll
            for (int nh = 0; nh < 2; nh++)
                ldmx4(bh[nh], sBh + (wn + nh * 16 + lmr) * LDB + (kk * 2 + lmc) * 16);
#pragma unroll
            for (int mi = 0; mi < 4; mi++) {
                uint32_t ah[4], al[4];
                uint32_t ro = (wm + mi * 16 + lmr) * LDB + (kk * 2 + lmc) * 16;
                ldmx4(ah, sAh + ro);
                ldmx4(al, sAl + ro);
#pragma unroll
                for (int nh = 0; nh < 2; nh++) {
                    mma16816(acc[mi][nh * 2 + 0], ah, bh[nh][0], bh[nh][2]);
                    mma16816(acc[mi][nh * 2 + 1], ah, bh[nh][1], bh[nh][3]);
                    mma16816(acc[mi][nh * 2 + 0], al, bh[nh][0], bh[nh][2]);
                    mma16816(acc[mi][nh * 2 + 1], al, bh[nh][1], bh[nh][3]);
                }
            }
        }
        __syncthreads();
    }

    const int er = lane >> 2, ec = (lane & 3) * 2;
#pragma unroll
    for (int mi = 0; mi < 4; mi++)
#pragma unroll
        for (int ni = 0; ni < 4; ni++) {
            size_t row = (size_t)(bm + wm + mi * 16 + er);
            size_t col = (size_t)(bn + wn + ni * 8 + ec);
            *(float2*)&C[row * N + col]       = make_float2(acc[mi][ni][0], acc[mi][ni][1]);
            *(float2*)&C[(row + 8) * N + col] = make_float2(acc[mi][ni][2], acc[mi][ni][3]);
        }
}

// fused Q/K/V projection: bx 0-15 -> Q, 16-19 -> K, 20-23 -> V
__global__ __launch_bounds__(256, 2) void gemm_qkv_kernel(
    const __half* __restrict__ Ahi, const __half* __restrict__ Alo,
    const __half* __restrict__ Wq, const __half* __restrict__ Wk,
    const __half* __restrict__ Wv,
    float* __restrict__ Cq, float* __restrict__ Ck, float* __restrict__ Cv)
{
    extern __shared__ char smemg[];
    const uint32_t sbase = smem_u32(smemg);
    const int bx = blockIdx.x, bm = blockIdx.y * 128;
    const __half* Bh; float* C; int N, bn;
    if (bx < 16)      { Bh = Wq; C = Cq; N = NH_ * HD_;  bn = bx * 128; }
    else if (bx < 20) { Bh = Wk; C = Ck; N = NKV_ * HD_; bn = (bx - 16) * 128; }
    else              { Bh = Wv; C = Cv; N = NKV_ * HD_; bn = (bx - 20) * 128; }
    gemm_body(Ahi, Alo, Bh, C, N, H_, bm, bn, sbase);
}

// plain GEMM (out-proj)
__global__ __launch_bounds__(256, 2) void gemm_fp16_kernel(
    const __half* __restrict__ Ahi, const __half* __restrict__ Alo,
    const __half* __restrict__ Bh, float* __restrict__ C, int N, int K)
{
    extern __shared__ char smemg[];
    const uint32_t sbase = smem_u32(smemg);
    gemm_body(Ahi, Alo, Bh, C, N, K, blockIdx.y * 128, blockIdx.x * 128, sbase);
}

// ============================================================================
// RoPE + split + relayout (Q): fp32 [B,S,nh,HD] -> fp16 hi/lo [B,nh,S,HD].
// ============================================================================
__global__ void rope_split_kernel(const float* __restrict__ x,
                                  __half* __restrict__ hi,
                                  __half* __restrict__ lo, int nheads)
{
    int idx = blockIdx.x * blockDim.x + threadIdx.x;
    int total = B_ * S_ * nheads * 32;
    if (idx >= total) return;
    int d = idx & 31;
    int r = idx >> 5;
    int h = r % nheads; r /= nheads;
    int s = r % S_;
    int b = r / S_;

    float inv = exp2f((float)d * -0.41524101186f);
    float fr = (float)s * inv;
    float c, sn;
    sincosf(fr, &sn, &c);

    size_t src = (((size_t)b * S_ + s) * nheads + h) * HD_;
    float x0 = x[src + d], x1 = x[src + d + 32];
    float y0 = x0 * c - x1 * sn;
    float y1 = x1 * c + x0 * sn;

    size_t dst = (((size_t)b * nheads + h) * S_ + s) * HD_;
    float h0 = __half2float(__float2half_rn(y0));
    float h1 = __half2float(__float2half_rn(y1));
    hi[dst + d]      = __float2half_rn(h0);
    hi[dst + d + 32] = __float2half_rn(h1);
    lo[dst + d]      = __float2half_rn(y0 - h0);
    lo[dst + d + 32] = __float2half_rn(y1 - h1);
}

// RoPE + round + relayout (K): scale folded here (1/8).
__global__ void rope_round_kernel(const float* __restrict__ x,
                                  __half* __restrict__ hi, int nheads, float scale)
{
    int idx = blockIdx.x * blockDim.x + threadIdx.x;
    int total = B_ * S_ * nheads * 32;
    if (idx >= total) return;
    int d = idx & 31;
    int r = idx >> 5;
    int h = r % nheads; r /= nheads;
    int s = r % S_;
    int b = r / S_;

    float inv = exp2f((float)d * -0.41524101186f);
    float fr = (float)s * inv;
    float c, sn;
    sincosf(fr, &sn, &c);

    size_t src = (((size_t)b * S_ + s) * nheads + h) * HD_;
    float x0 = x[src + d], x1 = x[src + d + 32];
    size_t dst = (((size_t)b * nheads + h) * S_ + s) * HD_;
    hi[dst + d]      = __float2half_rn((x0 * c - x1 * sn) * scale);
    hi[dst + d + 32] = __float2half_rn((x1 * c + x0 * sn) * scale);
}

// V round + relayout: fp32 [B,S,NKV,HD] -> fp16 [B,NKV,S,HD]
__global__ void roundv_kernel(const float* __restrict__ x,
                              __half* __restrict__ hi)
{
    int i = blockIdx.x * blockDim.x + threadIdx.x;
    const int total4 = B_ * S_ * NKV_ * HD_ / 4;
    if (i >= total4) return;
    int d4 = i & 15; int r = i >> 4;
    int h = r & 7; r >>= 3;
    int s = r & (S_ - 1);
    int b = r >> 11;

    float4 v = *(const float4*)(x + ((((size_t)b * S_ + s) * NKV_ + h) * HD_) + d4 * 4);
    size_t dst = (((size_t)b * NKV_ + h) * S_ + s) * HD_ + d4 * 4;
    *(uint32_t*)(hi + dst)     = pkhf(v.x, v.y);
    *(uint32_t*)(hi + dst + 2) = pkhf(v.z, v.w);
}

// ============================================================================
// Flash attention v2 on HMMA, 2-term fp16: S = (Qh+Ql)*Kh, O = (Ph+Pl)*Vh.
// Epilogue writes split fp16 hi/lo directly (feeds out-proj GEMM).
// ============================================================================
#define LDR   144
#define KVT   9216
#define KVSTG 18432
#define QOFF  36864
#define ATTN_SMEM 73728

#define KVPREF(buf, kv0v) do { \
    int r_ = tid >> 2; int qc_ = (tid & 3) * 32; \
    uint32_t so_ = sb + (buf) * KVSTG + r_ * LDR + qc_; \
    const char* kh_ = (const char*)(Kh + kvb + (size_t)((kv0v) + r_) * HD_) + qc_; \
    const char* vh_ = (const char*)(Vh + kvb + (size_t)((kv0v) + r_) * HD_) + qc_; \
    cp16(so_, kh_);         cp16(so_ + 16, kh_ + 16); \
    cp16(so_ + KVT, vh_);   cp16(so_ + KVT + 16, vh_ + 16); \
    CP_COMMIT(); \
} while (0)

__global__ __launch_bounds__(256, 2) void attn_hmma_kernel(
    const __half* __restrict__ Qh, const __half* __restrict__ Ql,
    const __half* __restrict__ Kh, const __half* __restrict__ Vh,
    __half* __restrict__ Ohh, __half* __restrict__ Ohl)
{
    extern __shared__ char sm[];
    const uint32_t sb = smem_u32(sm);
    const int qt = (S_ / 128 - 1) - blockIdx.x;
    const int h = blockIdx.y, b = blockIdx.z;
    const int hkv = h >> 2;
    const int tid = threadIdx.x, lane = tid & 31, w = tid >> 5;
    const int wq = w * 16, q0 = qt * 128;
    const int lmr = lane & 15, lmc = lane >> 4;
    const int g = lane >> 2, qd = lane & 3;
    const int vtr = lane & 7, vselk = (lane >> 3) & 1, vseln = lane >> 4;

    const __half* qhp = Qh + ((size_t)(b * NH_ + h) * S_ + q0) * HD_;
    const __half* qlp = Ql + ((size_t)(b * NH_ + h) * S_ + q0) * HD_;
    const size_t kvb = (size_t)(b * NKV_ + hkv) * S_ * HD_;

    // Q tiles into smem (once)
    {
        int r = tid >> 1;
        int cb = (tid & 1) * 64;
        uint32_t so = sb + QOFF + r * LDR + cb;
        const char* gh = (const char*)(qhp + (size_t)r * HD_) + cb;
        const char* gl = (const char*)(qlp + (size_t)r * HD_) + cb;
        cp16(so, gh);      cp16(so + 16, gh + 16);
        cp16(so + 32, gh + 32); cp16(so + 48, gh + 48);
        cp16(so + 18432, gl);      cp16(so + 18432 + 16, gl + 16);
        cp16(so + 18432 + 32, gl + 32); cp16(so + 18432 + 48, gl + 48);
        CP_COMMIT();
    }

    float m0 = -1e30f, m1 = -1e30f, l0 = 0.f, l1 = 0.f;
    float o[8][4];
#pragma unroll
    for (int nb = 0; nb < 8; nb++)
#pragma unroll
        for (int e = 0; e < 4; e++) o[nb][e] = 0.f;

    const int nch = 2 * (qt + 1);
    KVPREF(0, 0);

    for (int j = 0; j < nch; j++) {
        CP_WAIT0();
        __syncthreads();
        if (j + 1 < nch) KVPREF((j + 1) & 1, (j + 1) * 64);

        const uint32_t sKh = sb + (j & 1) * KVSTG;
        const uint32_t sVh = sKh + KVT;

        // ---- S = Q Kh^T (2 terms) ----
        float sc[8][4];
#pragma unroll
        for (int nb = 0; nb < 8; nb++)
#pragma unroll
            for (int e = 0; e < 4; e++) sc[nb][e] = 0.f;

#pragma unroll
        for (int kt = 0; kt < 4; kt++) {
            uint32_t qh_[4], ql_[4];
            uint32_t qro = QOFF + (wq + lmr) * LDR + (kt * 2 + lmc) * 16;
            ldmx4(qh_, sb + qro);
            ldmx4(ql_, sb + qro + 18432);
#pragma unroll
            for (int ng = 0; ng < 4; ng++) {
                uint32_t kh_[4];
                ldmx4(kh_, sKh + (ng * 16 + lmr) * LDR + (kt * 2 + lmc) * 16);
                mma16816(sc[2 * ng],     qh_, kh_[0], kh_[2]);
                mma16816(sc[2 * ng + 1], qh_, kh_[1], kh_[3]);
                mma16816(sc[2 * ng],     ql_, kh_[0], kh_[2]);
                mma16816(sc[2 * ng + 1], ql_, kh_[1], kh_[3]);
            }
        }

        // ---- causal mask ----
        const int kv0 = j * 64;
        if (kv0 + 63 > q0 + wq) {
            int row0 = q0 + wq + g;
#pragma unroll
            for (int nb = 0; nb < 8; nb++) {
                int col = kv0 + nb * 8 + qd * 2;
                if (col > row0)         sc[nb][0] = -1e30f;
                if (col + 1 > row0)     sc[nb][1] = -1e30f;
                if (col > row0 + 8)     sc[nb][2] = -1e30f;
                if (col + 1 > row0 + 8) sc[nb][3] = -1e30f;
            }
        }

        // ---- online softmax ----
        float mx0 = -1e30f, mx1 = -1e30f;
#pragma unroll
        for (int nb = 0; nb < 8; nb++) {
            mx0 = fmaxf(mx0, fmaxf(sc[nb][0], sc[nb][1]));
            mx1 = fmaxf(mx1, fmaxf(sc[nb][2], sc[nb][3]));
        }
        mx0 = fmaxf(mx0, __shfl_xor_sync(0xffffffffu, mx0, 1));
        mx0 = fmaxf(mx0, __shfl_xor_sync(0xffffffffu, mx0, 2));
        mx1 = fmaxf(mx1, __shfl_xor_sync(0xffffffffu, mx1, 1));
        mx1 = fmaxf(mx1, __shfl_xor_sync(0xffffffffu, mx1, 2));
        float nm0 = fmaxf(m0, mx0), nm1 = fmaxf(m1, mx1);
        float a0 = __expf(m0 - nm0), a1 = __expf(m1 - nm1);
        float rs0 = 0.f, rs1 = 0.f;
#pragma unroll
        for (int nb = 0; nb < 8; nb++) {
            sc[nb][0] = __expf(sc[nb][0] - nm0);
            sc[nb][1] = __expf(sc[nb][1] - nm0);
            sc[nb][2] = __expf(sc[nb][2] - nm1);
            sc[nb][3] = __expf(sc[nb][3] - nm1);
            rs0 += sc[nb][0] + sc[nb][1];
            rs1 += sc[nb][2] + sc[nb][3];
        }
        rs0 += __shfl_xor_sync(0xffffffffu, rs0, 1);
        rs0 += __shfl_xor_sync(0xffffffffu, rs0, 2);
        rs1 += __shfl_xor_sync(0xffffffffu, rs1, 1);
        rs1 += __shfl_xor_sync(0xffffffffu, rs1, 2);
        l0 = l0 * a0 + rs0; l1 = l1 * a1 + rs1;
        m0 = nm0; m1 = nm1;
#pragma unroll
        for (int nb = 0; nb < 8; nb++) {
            o[nb][0] *= a0; o[nb][1] *= a0;
            o[nb][2] *= a1; o[nb][3] *= a1;
        }

        // ---- O += P Vh (2 terms), P split from registers ----
#pragma unroll
        for (int kt = 0; kt < 4; kt++) {
            uint32_t pha[4], pla[4];
            splitpk(sc[2 * kt][0],     sc[2 * kt][1],     pha[0], pla[0]);
            splitpk(sc[2 * kt][2],     sc[2 * kt][3],     pha[1], pla[1]);
            splitpk(sc[2 * kt + 1][0], sc[2 * kt + 1][1], pha[2], pla[2]);
            splitpk(sc[2 * kt + 1][2], sc[2 * kt + 1][3], pha[3], pla[3]);
            uint32_t vrow = (kt * 16 + vselk * 8 + vtr) * LDR;
#pragma unroll
            for (int nb2 = 0; nb2 < 4; nb2++) {
                uint32_t vh_[4];
                ldmx4t(vh_, sVh + vrow + (nb2 * 2 + vseln) * 16);
                mma16816(o[2 * nb2],     pha, vh_[0], vh_[1]);
                mma16816(o[2 * nb2],     pla, vh_[0], vh_[1]);
                mma16816(o[2 * nb2 + 1], pha, vh_[2], vh_[3]);
                mma16816(o[2 * nb2 + 1], pla, vh_[2], vh_[3]);
            }
        }
    }

    // ---- epilogue: normalize + split to fp16 hi/lo directly ----
    float i0 = 1.f / l0, i1 = 1.f / l1;
    size_t base0 = ((size_t)(b * S_ + q0 + wq + g) * NH_ + h) * HD_;
    size_t base1 = base0 + (size_t)8 * NH_ * HD_;
#pragma unroll
    for (int nb = 0; nb < 8; nb++) {
        int col = nb * 8 + qd * 2;
        uint32_t hi, lo;
        splitpk(o[nb][0] * i0, o[nb][1] * i0, hi, lo);
        *(uint32_t*)(Ohh + base0 + col) = hi;
        *(uint32_t*)(Ohl + base0 + col) = lo;
        splitpk(o[nb][2] * i1, o[nb][3] * i1, hi, lo);
        *(uint32_t*)(Ohh + base1 + col) = hi;
        *(uint32_t*)(Ohl + base1 + col) = lo;
    }
}

// ============================================================================
extern "C" void kernel_launch(void* const* d_in, const int* in_sizes, int n_in,
                              void* d_out, int out_size)
{
    const float* hs = (const float*)d_in[0];
    const float* Wq = (const float*)d_in[1];
    const float* Wk = (const float*)d_in[2];
    const float* Wv = (const float*)d_in[3];
    const float* Wo = (const float*)d_in[4];
    float* out = (float*)d_out;

    float *qp, *kp, *vp;
    __half *hsh, *hsl, *wqh, *wkh, *wvh, *woh, *ohh, *ohl, *qh, *ql, *kh, *vh;
    cudaGetSymbolAddress((void**)&qp, g_q);
    cudaGetSymbolAddress((void**)&kp, g_k);
    cudaGetSymbolAddress((void**)&vp, g_v);
    cudaGetSymbolAddress((void**)&hsh, g_hs_hi);
    cudaGetSymbolAddress((void**)&hsl, g_hs_lo);
    cudaGetSymbolAddress((void**)&wqh, g_wq_hi);
    cudaGetSymbolAddress((void**)&wkh, g_wk_hi);
    cudaGetSymbolAddress((void**)&wvh, g_wv_hi);
    cudaGetSymbolAddress((void**)&woh, g_wo_hi);
    cudaGetSymbolAddress((void**)&ohh, g_oh_hi);
    cudaGetSymbolAddress((void**)&ohl, g_oh_lo);
    cudaGetSymbolAddress((void**)&qh, g_qh);
    cudaGetSymbolAddress((void**)&ql, g_ql);
    cudaGetSymbolAddress((void**)&kh, g_kh2);
    cudaGetSymbolAddress((void**)&vh, g_vh2);

    const int M = B_ * S_;
    const int nHS = B_ * S_ * H_;

    cudaFuncSetAttribute(gemm_qkv_kernel, cudaFuncAttributeMaxDynamicSharedMemorySize, GEMM_SMEM);
    cudaFuncSetAttribute(gemm_fp16_kernel, cudaFuncAttributeMaxDynamicSharedMemorySize, GEMM_SMEM);
    cudaFuncSetAttribute(attn_hmma_kernel, cudaFuncAttributeMaxDynamicSharedMemorySize, ATTN_SMEM);

    // split hidden states; round all weights (one launch)
    split_kernel<<<nHS / 4 / 256, 256>>>(hs, hsh, hsl, nHS / 4);
    round4_kernel<<<(N4_WQ + N4_WK + N4_WV + N4_WO) / 256, 256>>>(
        Wq, Wk, Wv, Wo, wqh, wkh, wvh, woh);

    // fused QKV projection
    gemm_qkv_kernel<<<dim3(24, 32), 256, GEMM_SMEM>>>(hsh, hsl, wqh, wkh, wvh, qp, kp, vp);

    // RoPE: Q split (unscaled); K rounded with 1/8 scale; V rounded
    rope_split_kernel<<<(B_ * S_ * NH_ * 32) / 256, 256>>>(qp, qh, ql, NH_);
    rope_round_kernel<<<(B_ * S_ * NKV_ * 32) / 256, 256>>>(kp, kh, NKV_, 0.125f);
    roundv_kernel<<<(B_ * S_ * NKV_ * HD_ / 4) / 256, 256>>>(vp, vh);

    // attention (writes split fp16 hi/lo directly)
    attn_hmma_kernel<<<dim3(S_ / 128, NH_, B_), 256, ATTN_SMEM>>>(qh, ql, kh, vh, ohh, ohl);

    // out-proj
    gemm_fp16_kernel<<<dim3(16, 32), 256, GEMM_SMEM>>>(ohh, ohl, woh, out, H_, H_);
}